// round 8
// baseline (speedup 1.0000x reference)
#include <cuda_runtime.h>
#include <cuda_bf16.h>
#include <cstdint>
#include <cfloat>
#include <math.h>

// Problem constants
#define BB 64
#define NN 2000
#define DD 128
#define HH 8
#define DHH 16
#define BEAM 16
#define NCHUNK 8
#define CHN 250   // nodes per chunk (8*250 = 2000)

// Scratch (no cudaMalloc allowed)
// Feature-major kvl: g_kt[b][f][n], f 0..383 (gk 0..127, gv 128..255, lk 256..383)
__device__ float g_kt[(size_t)BB * 384 * NN + 64];        // ~196.6 MB
__device__ unsigned char g_mask[(size_t)BB * BEAM * NN];  // normalized mask
__device__ int g_isbool;                                  // zero-init; monotone OR
__device__ float g_fpart[BB * NCHUNK * DD];               // mean partial sums
__device__ float g_q[BB * BEAM * DD];                     // queries
__device__ float g_pm[BB * NCHUNK * HH * BEAM];           // partial softmax max
__device__ float g_ps[BB * NCHUNK * HH * BEAM];           // partial softmax sum
__device__ float g_pacc[BB * NCHUNK * HH * BEAM * DHH];   // partial weighted V
__device__ float g_glim[BB * BEAM * DD];                  // glimpse vectors

// fma-pipe exp for x <= 0 (clamped); rel err ~3e-8. No MUFU.
__device__ __forceinline__ float fexp(float x) {
  x = fmaxf(x, -80.f);
  float y = x * 1.4426950408889634f;
  float r = y + 12582912.f;
  float k = r - 12582912.f;
  float f = y - k;
  float p = 1.5403530393381609e-4f;
  p = fmaf(p, f, 1.3333558146428443e-3f);
  p = fmaf(p, f, 9.6181291976353993e-3f);
  p = fmaf(p, f, 5.5504108664821580e-2f);
  p = fmaf(p, f, 2.4022650695910071e-1f);
  p = fmaf(p, f, 6.9314718055994531e-1f);
  p = fmaf(p, f, 1.0f);
  int e = (int)k;
  return p * __int_as_float((e + 127) << 23);
}

__device__ __forceinline__ unsigned int f2tf32(float x) {
  unsigned int r;
  asm("cvt.rna.tf32.f32 %0, %1;" : "=r"(r) : "f"(x));
  return r;
}

__device__ __forceinline__ void mma_tf32(float* c, unsigned int a0, unsigned int a1,
                                         unsigned int a2, unsigned int a3,
                                         unsigned int b0, unsigned int b1) {
  asm volatile(
      "mma.sync.aligned.m16n8k8.row.col.f32.tf32.tf32.f32 "
      "{%0,%1,%2,%3},{%4,%5,%6,%7},{%8,%9},{%0,%1,%2,%3};"
      : "+f"(c[0]), "+f"(c[1]), "+f"(c[2]), "+f"(c[3])
      : "r"(a0), "r"(a1), "r"(a2), "r"(a3), "r"(b0), "r"(b1));
}

// ---------------------------------------------------------------------------
// Mask detection + normalization. g_isbool starts 0 (module zero-init) and is
// only ever OR'd with the (constant-input) detection result -> deterministic.
// ---------------------------------------------------------------------------
__global__ __launch_bounds__(256) void detect_mask_kernel(const unsigned char* __restrict__ m) {
  int base = blockIdx.x * (1 << 14);
  int local = 0;
  for (int i = threadIdx.x; i < (1 << 14); i += 256) {
    int idx = base + i;
    if ((idx & 3) && m[idx]) local = 1;
  }
  if (__syncthreads_or(local)) {
    if (threadIdx.x == 0) g_isbool = 1;
  }
}

__global__ __launch_bounds__(256) void convert_mask_kernel(const unsigned char* __restrict__ m) {
  int i = blockIdx.x * 256 + threadIdx.x;
  if (i >= BB * BEAM * NN) return;
  if (g_isbool) g_mask[i] = (m[i] != 0);
  else g_mask[i] = (((const int*)m)[i] != 0);
}

// ---------------------------------------------------------------------------
// K1: mean partial sums: g_fpart[b][c][d] = sum_{n in chunk c} emb[b,n,d]
// grid (64, 8), 512 threads: 4 rows in flight.
// ---------------------------------------------------------------------------
__global__ __launch_bounds__(512) void fpart_kernel(const float* __restrict__ emb) {
  int b = blockIdx.x, c = blockIdx.y;
  int r = threadIdx.x >> 7, d = threadIdx.x & 127;
  __shared__ float part[4][DD];
  const float* p = emb + ((size_t)b * NN + c * CHN) * DD + d;
  float s = 0.f;
#pragma unroll 4
  for (int n = r; n < CHN; n += 4) s += p[(size_t)n * DD];
  part[r][d] = s;
  __syncthreads();
  if (r == 0)
    g_fpart[(b * NCHUNK + c) * DD + d] = part[0][d] + part[1][d] + part[2][d] + part[3][d];
}

// ---------------------------------------------------------------------------
// K2: kvl = emb[128000,128] @ W_node[128,384] via 3xTF32 tensor-core mma,
// output feature-major to g_kt. CTA tile 128(m) x 128(f) x K=128 (staged 32).
// 8 warps: warp (wm = w&3, wn = w>>2) -> 32m x 64n warp tile.
// grid (3, 1000), 256 threads, 67.5 KB dynamic smem.
// ---------------------------------------------------------------------------
__global__ __launch_bounds__(256) void kvl_gemm_tf32(
    const float* __restrict__ A, const float* __restrict__ W) {
  extern __shared__ float smem[];
  float* As_hi = smem;                 // [32][132] (k x m)
  float* As_lo = As_hi + 32 * 132;
  float* Bs_hi = As_lo + 32 * 132;     // [32][132] (k x n)
  float* Bs_lo = Bs_hi + 32 * 132;

  const int m0 = blockIdx.y * 128;
  const int n0 = blockIdx.x * 128;
  const int tid = threadIdx.x;
  const int wid = tid >> 5, lane = tid & 31;
  const int wm = wid & 3, wn = wid >> 2;
  const int lq = lane >> 2, lr4 = lane & 3;
  // loaders
  const int lrA = tid >> 3;            // 0..31 (m row group)
  const int lcA = (tid & 7) * 4;       // k float4 offset
  const int wrB = tid >> 5;            // 0..7  (k row group)
  const int wcB = (tid & 31) * 4;      // n float4 offset

  float acc[2][8][4];
#pragma unroll
  for (int mf = 0; mf < 2; mf++)
#pragma unroll
    for (int nf = 0; nf < 8; nf++)
#pragma unroll
      for (int j = 0; j < 4; j++) acc[mf][nf][j] = 0.f;

  for (int kb = 0; kb < 128; kb += 32) {
    // A tile: transpose to As[k][m], split hi/lo
#pragma unroll
    for (int p = 0; p < 4; p++) {
      int row = lrA + 32 * p;
      float4 v = *(const float4*)&A[(size_t)(m0 + row) * 128 + kb + lcA];
      float vv[4] = {v.x, v.y, v.z, v.w};
#pragma unroll
      for (int j = 0; j < 4; j++) {
        float hi = __uint_as_float(f2tf32(vv[j]));
        As_hi[(lcA + j) * 132 + row] = hi;
        As_lo[(lcA + j) * 132 + row] = __uint_as_float(f2tf32(vv[j] - hi));
      }
    }
    // B tile: Bs[k][n], split hi/lo (float4 stores)
#pragma unroll
    for (int p = 0; p < 4; p++) {
      int kr = wrB + 8 * p;
      float4 v = *(const float4*)&W[(size_t)(kb + kr) * 384 + n0 + wcB];
      float vv[4] = {v.x, v.y, v.z, v.w};
      float4 h4, l4;
      float* hp = (float*)&h4;
      float* lp = (float*)&l4;
#pragma unroll
      for (int j = 0; j < 4; j++) {
        float hi = __uint_as_float(f2tf32(vv[j]));
        hp[j] = hi;
        lp[j] = __uint_as_float(f2tf32(vv[j] - hi));
      }
      *(float4*)&Bs_hi[kr * 132 + wcB] = h4;
      *(float4*)&Bs_lo[kr * 132 + wcB] = l4;
    }
    __syncthreads();

#pragma unroll
    for (int ks = 0; ks < 4; ks++) {
      const int k0 = ks * 8;
      unsigned int a_hi[2][4], a_lo[2][4];
      const int kAa = (k0 + lr4) * 132;
      const int kAb = (k0 + 4 + lr4) * 132;
#pragma unroll
      for (int mf = 0; mf < 2; mf++) {
        const int rb = 32 * wm + 16 * mf;
        a_hi[mf][0] = __float_as_uint(As_hi[kAa + rb + lq]);
        a_hi[mf][1] = __float_as_uint(As_hi[kAa + rb + lq + 8]);
        a_hi[mf][2] = __float_as_uint(As_hi[kAb + rb + lq]);
        a_hi[mf][3] = __float_as_uint(As_hi[kAb + rb + lq + 8]);
        a_lo[mf][0] = __float_as_uint(As_lo[kAa + rb + lq]);
        a_lo[mf][1] = __float_as_uint(As_lo[kAa + rb + lq + 8]);
        a_lo[mf][2] = __float_as_uint(As_lo[kAb + rb + lq]);
        a_lo[mf][3] = __float_as_uint(As_lo[kAb + rb + lq + 8]);
      }
#pragma unroll
      for (int nf = 0; nf < 8; nf++) {
        const int cb = 64 * wn + 8 * nf;
        unsigned int b_hi0 = __float_as_uint(Bs_hi[kAa + cb + lq]);
        unsigned int b_hi1 = __float_as_uint(Bs_hi[kAb + cb + lq]);
        unsigned int b_lo0 = __float_as_uint(Bs_lo[kAa + cb + lq]);
        unsigned int b_lo1 = __float_as_uint(Bs_lo[kAb + cb + lq]);
#pragma unroll
        for (int mf = 0; mf < 2; mf++) {
          mma_tf32(acc[mf][nf], a_hi[mf][0], a_hi[mf][1], a_hi[mf][2], a_hi[mf][3], b_hi0, b_hi1);
          mma_tf32(acc[mf][nf], a_hi[mf][0], a_hi[mf][1], a_hi[mf][2], a_hi[mf][3], b_lo0, b_lo1);
          mma_tf32(acc[mf][nf], a_lo[mf][0], a_lo[mf][1], a_lo[mf][2], a_lo[mf][3], b_hi0, b_hi1);
        }
      }
    }
    __syncthreads();
  }

  // --- transpose epilogue: 4 chunks of 32 feature-rows through As_hi ---
#pragma unroll 1
  for (int c = 0; c < 4; c++) {
    if (wn == (c >> 1)) {
#pragma unroll
      for (int nfl = 0; nfl < 4; nfl++) {
        const int nf = 4 * (c & 1) + nfl;
#pragma unroll
        for (int mf = 0; mf < 2; mf++)
#pragma unroll
          for (int j = 0; j < 4; j++) {
            int fr = 8 * nfl + 2 * lr4 + (j & 1);
            int ml = 32 * wm + 16 * mf + lq + 8 * (j >> 1);
            As_hi[fr * 132 + ml] = acc[mf][nf][j];
          }
      }
    }
    __syncthreads();
#pragma unroll
    for (int j4 = 0; j4 < 4; j4++) {
      int fr = (tid >> 5) + 8 * j4;
      int mloc = (tid & 31) * 4;
      int gf = n0 + 32 * c + fr;
#pragma unroll
      for (int e = 0; e < 4; e++) {
        int m = m0 + mloc + e;
        int b = m / NN;
        int n = m - b * NN;
        g_kt[((size_t)b * 384 + gf) * NN + n] = As_hi[fr * 132 + mloc + e];
      }
    }
    __syncthreads();
  }
}

// ---------------------------------------------------------------------------
// K3: query build (unchanged)
// ---------------------------------------------------------------------------
__global__ __launch_bounds__(128) void query_kernel(
    const float* __restrict__ emb, const float* __restrict__ W_fixed,
    const float* __restrict__ W_step, const int* __restrict__ seq) {
  const int bm = blockIdx.x;
  const int b = bm >> 4;
  const int d = threadIdx.x;
  __shared__ float mean[DD], ef[DD], el[DD];
  float s = 0.f;
#pragma unroll
  for (int c = 0; c < NCHUNK; c++) s += g_fpart[(b * NCHUNK + c) * DD + d];
  mean[d] = s * (1.0f / (float)NN);
  int fidx = seq[bm * 2];
  int lidx = seq[bm * 2 + 1];
  ef[d] = emb[((size_t)b * NN + fidx) * DD + d];
  el[d] = emb[((size_t)b * NN + lidx) * DD + d];
  __syncthreads();
  float a = 0.f;
#pragma unroll 8
  for (int k = 0; k < DD; k++) a = fmaf(mean[k], W_fixed[k * DD + d], a);
#pragma unroll 8
  for (int k = 0; k < DD; k++) a = fmaf(ef[k], W_step[k * DD + d], a);
#pragma unroll 8
  for (int k = 0; k < DD; k++) a = fmaf(el[k], W_step[(DD + k) * DD + d], a);
  g_q[bm * DD + d] = a;
}

// ---------------------------------------------------------------------------
// K4: beam-batched glimpse partials (unchanged from round 6)
// ---------------------------------------------------------------------------
__global__ __launch_bounds__(256) void glimpse_kernel() {
  const int b = blockIdx.x, c = blockIdx.y;
  const int n0 = c * CHN;
  const int tid = threadIdx.x;
  const int h = tid >> 5;
  const int lane = tid & 31;

  __shared__ float q_s[BEAM][DD];
  __shared__ unsigned char mk[BEAM][260];
  __shared__ float s_s[HH][BEAM][33];
  __shared__ float v_s[HH][DHH][33];

  for (int i = tid; i < BEAM * DD; i += 256) q_s[i >> 7][i & 127] = g_q[b * BEAM * DD + i];
  for (int i = tid; i < BEAM * 256; i += 256) {
    int m = i >> 8, n = i & 255;
    mk[m][n] = (n < CHN) ? g_mask[((size_t)(b * BEAM + m)) * NN + n0 + n] : (unsigned char)1;
  }
  __syncthreads();

  const float* __restrict__ gk = g_kt + ((size_t)b * 384 + h * DHH) * NN;
  const float* __restrict__ gv = g_kt + ((size_t)b * 384 + 128 + h * DHH) * NN;

  const int mown = lane & 15;
  const int tg = lane >> 4;
  float m_run = -1e30f, s_run = 0.f;
  float acc[8];
#pragma unroll
  for (int j = 0; j < 8; j++) acc[j] = 0.f;

#pragma unroll 1
  for (int g = 0; g < 8; g++) {
    const int nl = g * 32 + lane;
    const bool valid = nl < CHN;
    const int n = n0 + nl;
    float kf[DHH];
#pragma unroll
    for (int t = 0; t < DHH; t++) kf[t] = valid ? gk[(size_t)t * NN + n] : 0.f;
#pragma unroll
    for (int t = 0; t < DHH; t++) v_s[h][t][lane] = valid ? gv[(size_t)t * NN + n] : 0.f;
#pragma unroll
    for (int mi = 0; mi < BEAM; mi++) {
      const float4* qv = (const float4*)&q_s[mi][h * DHH];
      float s = 0.f;
#pragma unroll
      for (int t4 = 0; t4 < 4; t4++) {
        float4 q4 = qv[t4];
        s = fmaf(q4.x, kf[t4 * 4 + 0], s);
        s = fmaf(q4.y, kf[t4 * 4 + 1], s);
        s = fmaf(q4.z, kf[t4 * 4 + 2], s);
        s = fmaf(q4.w, kf[t4 * 4 + 3], s);
      }
      s_s[h][mi][lane] = valid ? s * 0.25f : -1e30f;
    }
    __syncwarp();
    float gm = -1e30f;
#pragma unroll
    for (int j = 0; j < 32; j++) {
      float s = mk[mown][g * 32 + j] ? -1e30f : s_s[h][mown][j];
      s_s[h][mown][j] = s;
      gm = fmaxf(gm, s);
    }
    float mnew = fmaxf(m_run, gm);
    float scale = fexp(m_run - mnew);
    float ssum = 0.f;
#pragma unroll
    for (int j = 0; j < 8; j++) acc[j] *= scale;
#pragma unroll
    for (int j = 0; j < 32; j++) {
      float p = fexp(s_s[h][mown][j] - mnew);
      ssum += p;
#pragma unroll
      for (int jj = 0; jj < 8; jj++) acc[jj] = fmaf(p, v_s[h][tg * 8 + jj][j], acc[jj]);
    }
    s_run = s_run * scale + ssum;
    m_run = mnew;
    __syncwarp();
  }
  const int idx = ((b * NCHUNK + c) * HH + h) * BEAM + mown;
  if (tg == 0) { g_pm[idx] = m_run; g_ps[idx] = s_run; }
#pragma unroll
  for (int j = 0; j < 8; j++) g_pacc[idx * DHH + tg * 8 + j] = acc[j];
}

// ---------------------------------------------------------------------------
// K5: reduce partials -> heads -> glimpse = heads @ W_out (unchanged)
// ---------------------------------------------------------------------------
__global__ __launch_bounds__(128) void reduce_kernel(const float* __restrict__ W_out) {
  const int bm = blockIdx.x;
  const int b = bm >> 4;
  const int m = bm & 15;
  const int d = threadIdx.x;
  const int h = d >> 4;
  const int t = d & 15;
  __shared__ float heads[DD];
  float M = -1e30f, S = 0.f, A = 0.f;
#pragma unroll
  for (int c = 0; c < NCHUNK; c++) {
    const int idx = ((b * NCHUNK + c) * HH + h) * BEAM + m;
    float mc = g_pm[idx];
    float sc = g_ps[idx];
    float ac = g_pacc[idx * DHH + t];
    float mn = fmaxf(M, mc);
    float e1 = fexp(M - mn);
    float e2 = fexp(mc - mn);
    S = S * e1 + sc * e2;
    A = A * e1 + ac * e2;
    M = mn;
  }
  heads[d] = A / S;
  __syncthreads();
  float a = 0.f;
#pragma unroll 8
  for (int k = 0; k < DD; k++) a = fmaf(heads[k], W_out[k * DD + d], a);
  g_glim[bm * DD + d] = a;
}

// ---------------------------------------------------------------------------
// K6: beam-batched logits (unchanged)
// ---------------------------------------------------------------------------
__global__ __launch_bounds__(256) void logits_kernel(float* __restrict__ out) {
  const int b = blockIdx.x, c = blockIdx.y;
  const int tid = threadIdx.x;
  __shared__ float glim_s[BEAM][DD];
  __shared__ unsigned char mk[BEAM][260];
  for (int i = tid; i < BEAM * DD; i += 256) glim_s[i >> 7][i & 127] = g_glim[b * BEAM * DD + i];
  for (int i = tid; i < BEAM * 256; i += 256) {
    int m = i >> 8, n = i & 255;
    mk[m][n] = (n < CHN) ? g_mask[((size_t)(b * BEAM + m)) * NN + c * CHN + n] : (unsigned char)1;
  }
  __syncthreads();
  if (tid >= CHN) return;
  const int n = c * CHN + tid;
  const float* __restrict__ lk = g_kt + ((size_t)b * 384 + 256) * NN + n;
  float s[BEAM];
#pragma unroll
  for (int m = 0; m < BEAM; m++) s[m] = 0.f;
#pragma unroll 4
  for (int f = 0; f < DD; f += 4) {
    float l0 = lk[(size_t)(f + 0) * NN];
    float l1 = lk[(size_t)(f + 1) * NN];
    float l2 = lk[(size_t)(f + 2) * NN];
    float l3 = lk[(size_t)(f + 3) * NN];
#pragma unroll
    for (int m = 0; m < BEAM; m++) {
      float4 g4 = *(const float4*)&glim_s[m][f];
      s[m] = fmaf(g4.x, l0, s[m]);
      s[m] = fmaf(g4.y, l1, s[m]);
      s[m] = fmaf(g4.z, l2, s[m]);
      s[m] = fmaf(g4.w, l3, s[m]);
    }
  }
  const float invsq = 0.08838834764831845f;
#pragma unroll
  for (int m = 0; m < BEAM; m++) {
    float v = 10.f * tanhf(s[m] * invsq);
    if (mk[m][tid]) v = -FLT_MAX;
    out[((size_t)(b * BEAM + m)) * NN + n] = v;
  }
}

// ---------------------------------------------------------------------------
// K7: finalize per (b,m): log_softmax + top3 (unchanged)
// ---------------------------------------------------------------------------
__global__ __launch_bounds__(256) void finalize_kernel(float* __restrict__ out) {
  const int bm = blockIdx.x;
  const int tid = threadIdx.x;
  float* __restrict__ lp = out + (size_t)bm * NN;
  __shared__ float logits[NN];
  __shared__ float red[256];
  __shared__ float stv[256][3];
  __shared__ int sti[256][3];

  float tv0 = -INFINITY, tv1 = -INFINITY, tv2 = -INFINITY;
  int ti0 = 0, ti1 = 0, ti2 = 0;
  float lmax = -INFINITY;
#pragma unroll 1
  for (int k = 0; k < 8; k++) {
    const int n = tid + 256 * k;
    if (n >= NN) break;
    float v = lp[n];
    logits[n] = v;
    lmax = fmaxf(lmax, v);
    if (v > tv0) { tv2 = tv1; ti2 = ti1; tv1 = tv0; ti1 = ti0; tv0 = v; ti0 = n; }
    else if (v > tv1) { tv2 = tv1; ti2 = ti1; tv1 = v; ti1 = n; }
    else if (v > tv2) { tv2 = v; ti2 = n; }
  }
  stv[tid][0] = tv0; stv[tid][1] = tv1; stv[tid][2] = tv2;
  sti[tid][0] = ti0; sti[tid][1] = ti1; sti[tid][2] = ti2;
  red[tid] = lmax;
  __syncthreads();
  for (int s2 = 128; s2 > 0; s2 >>= 1) {
    if (tid < s2) red[tid] = fmaxf(red[tid], red[tid + s2]);
    __syncthreads();
  }
  lmax = red[0];
  __syncthreads();
  float lsum = 0.f;
  for (int n = tid; n < NN; n += 256) lsum += fexp(logits[n] - lmax);
  red[tid] = lsum;
  __syncthreads();
  for (int s2 = 128; s2 > 0; s2 >>= 1) {
    if (tid < s2) red[tid] += red[tid + s2];
    __syncthreads();
  }
  const float lse = lmax + __logf(red[0]);

  for (int n = tid; n < NN; n += 256) lp[n] = logits[n] - lse;

  for (int s2 = 128; s2 > 0; s2 >>= 1) {
    if (tid < s2) {
      float a0 = stv[tid][0], a1 = stv[tid][1], a2 = stv[tid][2];
      int i0 = sti[tid][0], i1 = sti[tid][1], i2 = sti[tid][2];
#pragma unroll
      for (int j = 0; j < 3; j++) {
        float v = stv[tid + s2][j];
        int ii = sti[tid + s2][j];
        if (v > a0) { a2 = a1; i2 = i1; a1 = a0; i1 = i0; a0 = v; i0 = ii; }
        else if (v > a1) { a2 = a1; i2 = i1; a1 = v; i1 = ii; }
        else if (v > a2) { a2 = v; i2 = ii; }
      }
      stv[tid][0] = a0; stv[tid][1] = a1; stv[tid][2] = a2;
      sti[tid][0] = i0; sti[tid][1] = i1; sti[tid][2] = i2;
    }
    __syncthreads();
  }
  if (tid == 0) {
    float* tvo = out + (size_t)BB * BEAM * NN + bm * 3;
    float* tio = out + (size_t)BB * BEAM * NN + (size_t)BB * BEAM * 3 + bm * 3;
    tvo[0] = stv[0][0] - lse; tvo[1] = stv[0][1] - lse; tvo[2] = stv[0][2] - lse;
    tio[0] = (float)sti[0][0]; tio[1] = (float)sti[0][1]; tio[2] = (float)sti[0][2];
  }
}

// ---------------------------------------------------------------------------
extern "C" void kernel_launch(void* const* d_in, const int* in_sizes, int n_in,
                              void* d_out, int out_size) {
  const float* emb = nullptr;
  const float* W_node = nullptr;
  const float* W_fixed = nullptr;
  const float* W_step = nullptr;
  const float* W_out = nullptr;
  const int* seq = nullptr;
  const unsigned char* mask = nullptr;
  for (int i = 0; i < n_in; i++) {
    int sz = in_sizes[i];
    if (sz == BB * NN * DD) emb = (const float*)d_in[i];
    else if (sz == DD * 3 * DD) W_node = (const float*)d_in[i];
    else if (sz == 2 * DD * DD) W_step = (const float*)d_in[i];
    else if (sz == BB * BEAM * 2) seq = (const int*)d_in[i];
    else if (sz == BB * BEAM * NN) mask = (const unsigned char*)d_in[i];
    else if (sz == DD * DD) {
      if (!W_fixed) W_fixed = (const float*)d_in[i];
      else W_out = (const float*)d_in[i];
    }
  }
  float* out = (float*)d_out;

  static int smem_set = 0;
  if (!smem_set) {
    cudaFuncSetAttribute(kvl_gemm_tf32, cudaFuncAttributeMaxDynamicSharedMemorySize,
                         4 * 32 * 132 * (int)sizeof(float));
    smem_set = 1;
  }

  detect_mask_kernel<<<64, 256>>>(mask);
  convert_mask_kernel<<<(BB * BEAM * NN + 255) / 256, 256>>>(mask);
  fpart_kernel<<<dim3(BB, NCHUNK), 512>>>(emb);
  kvl_gemm_tf32<<<dim3(3, (BB * NN) / 128), 256, 4 * 32 * 132 * sizeof(float)>>>(emb, W_node);
  query_kernel<<<BB * BEAM, 128>>>(emb, W_fixed, W_step, seq);
  glimpse_kernel<<<dim3(BB, NCHUNK), 256>>>();
  reduce_kernel<<<BB * BEAM, 128>>>(W_out);
  logits_kernel<<<dim3(BB, NCHUNK), 256>>>(out);
  finalize_kernel<<<BB * BEAM, 256>>>(out);
}

// round 9
// speedup vs baseline: 1.1339x; 1.1339x over previous
#include <cuda_runtime.h>
#include <cuda_bf16.h>
#include <cstdint>
#include <cfloat>
#include <math.h>

// Problem constants
#define BB 64
#define NN 2000
#define DD 128
#define HH 8
#define DHH 16
#define BEAM 16
#define NCHUNK 8
#define CHN 250   // nodes per chunk (8*250 = 2000)

// Scratch (no cudaMalloc allowed)
// Feature-major kvl: g_kt[b][f][n], f 0..383 (gk 0..127, gv 128..255, lk 256..383)
__device__ float g_kt[(size_t)BB * 384 * NN + 64];        // ~196.6 MB
__device__ unsigned char g_mask[(size_t)BB * BEAM * NN];  // normalized mask
__device__ int g_isbool;                                  // zero-init; monotone OR
__device__ float g_fpart[BB * NCHUNK * DD];               // mean partial sums
__device__ float g_q[BB * BEAM * DD];                     // queries
__device__ float g_pm[BB * NCHUNK * HH * BEAM];           // partial softmax max
__device__ float g_ps[BB * NCHUNK * HH * BEAM];           // partial softmax sum
__device__ float g_pacc[BB * NCHUNK * HH * BEAM * DHH];   // partial weighted V
__device__ float g_glim[BB * BEAM * DD];                  // glimpse vectors

// fma-pipe exp for x <= 0 (clamped); rel err ~3e-8. No MUFU.
__device__ __forceinline__ float fexp(float x) {
  x = fmaxf(x, -80.f);
  float y = x * 1.4426950408889634f;
  float r = y + 12582912.f;
  float k = r - 12582912.f;
  float f = y - k;
  float p = 1.5403530393381609e-4f;
  p = fmaf(p, f, 1.3333558146428443e-3f);
  p = fmaf(p, f, 9.6181291976353993e-3f);
  p = fmaf(p, f, 5.5504108664821580e-2f);
  p = fmaf(p, f, 2.4022650695910071e-1f);
  p = fmaf(p, f, 6.9314718055994531e-1f);
  p = fmaf(p, f, 1.0f);
  int e = (int)k;
  return p * __int_as_float((e + 127) << 23);
}

__device__ __forceinline__ unsigned int f2tf32(float x) {
  unsigned int r;
  asm("cvt.rna.tf32.f32 %0, %1;" : "=r"(r) : "f"(x));
  return r;
}

__device__ __forceinline__ void mma_tf32(float* c, unsigned int a0, unsigned int a1,
                                         unsigned int a2, unsigned int a3,
                                         unsigned int b0, unsigned int b1) {
  asm volatile(
      "mma.sync.aligned.m16n8k8.row.col.f32.tf32.tf32.f32 "
      "{%0,%1,%2,%3},{%4,%5,%6,%7},{%8,%9},{%0,%1,%2,%3};"
      : "+f"(c[0]), "+f"(c[1]), "+f"(c[2]), "+f"(c[3])
      : "r"(a0), "r"(a1), "r"(a2), "r"(a3), "r"(b0), "r"(b1));
}

__device__ __forceinline__ void cp16(void* sptr, const void* gptr) {
  unsigned int saddr = (unsigned int)__cvta_generic_to_shared(sptr);
  asm volatile("cp.async.cg.shared.global [%0], [%1], 16;" :: "r"(saddr), "l"(gptr));
}

// ---------------------------------------------------------------------------
// Mask detection + normalization (unchanged; validated)
// ---------------------------------------------------------------------------
__global__ __launch_bounds__(256) void detect_mask_kernel(const unsigned char* __restrict__ m) {
  int base = blockIdx.x * (1 << 14);
  int local = 0;
  for (int i = threadIdx.x; i < (1 << 14); i += 256) {
    int idx = base + i;
    if ((idx & 3) && m[idx]) local = 1;
  }
  if (__syncthreads_or(local)) {
    if (threadIdx.x == 0) g_isbool = 1;
  }
}

__global__ __launch_bounds__(256) void convert_mask_kernel(const unsigned char* __restrict__ m) {
  int i = blockIdx.x * 256 + threadIdx.x;
  if (i >= BB * BEAM * NN) return;
  if (g_isbool) g_mask[i] = (m[i] != 0);
  else g_mask[i] = (((const int*)m)[i] != 0);
}

// ---------------------------------------------------------------------------
// K1: mean partial sums (unchanged from round 8: 512 threads, 4 rows in flight)
// ---------------------------------------------------------------------------
__global__ __launch_bounds__(512) void fpart_kernel(const float* __restrict__ emb) {
  int b = blockIdx.x, c = blockIdx.y;
  int r = threadIdx.x >> 7, d = threadIdx.x & 127;
  __shared__ float part[4][DD];
  const float* p = emb + ((size_t)b * NN + c * CHN) * DD + d;
  float s = 0.f;
#pragma unroll 4
  for (int n = r; n < CHN; n += 4) s += p[(size_t)n * DD];
  part[r][d] = s;
  __syncthreads();
  if (r == 0)
    g_fpart[(b * NCHUNK + c) * DD + d] = part[0][d] + part[1][d] + part[2][d] + part[3][d];
}

// ---------------------------------------------------------------------------
// K2: kvl GEMM, 3xTF32, cp.async double-buffered, raw-f32 smem,
// fragment-time hi/lo conversion. CTA tile 128m x 128f, K staged 32.
// smem: As[2][128][36] + Bs[2][32][136] = 70 KB dynamic. 2 CTAs/SM.
// ---------------------------------------------------------------------------
#define AS_LD 36
#define BS_LD 136
#define AS_FLOATS (128 * AS_LD)   // 4608
#define BS_FLOATS (32 * BS_LD)    // 4352
#define SMEM_FLOATS (2 * (AS_FLOATS + BS_FLOATS))  // 17920 floats = 71680 B

__global__ __launch_bounds__(256, 2) void kvl_gemm_tf32(
    const float* __restrict__ A, const float* __restrict__ W) {
  extern __shared__ float smem[];
  const int m0 = blockIdx.y * 128;
  const int n0 = blockIdx.x * 128;
  const int tid = threadIdx.x;
  const int wid = tid >> 5, lane = tid & 31;
  const int wm = wid & 3, wn = wid >> 2;
  const int lq = lane >> 2, lr4 = lane & 3;

  float acc[2][8][4];
#pragma unroll
  for (int mf = 0; mf < 2; mf++)
#pragma unroll
    for (int nf = 0; nf < 8; nf++)
#pragma unroll
      for (int j = 0; j < 4; j++) acc[mf][nf][j] = 0.f;

  // async loader: stage st gets K-slab starting at kb
  auto load_stage = [&](int st, int kb) {
    float* As = smem + st * AS_FLOATS;
    float* Bs = smem + 2 * AS_FLOATS + st * BS_FLOATS;
#pragma unroll
    for (int i = 0; i < 4; i++) {
      int c = tid + 256 * i;                // 0..1023
      int arow = c >> 3, kc = (c & 7) << 2; // 128 rows x 8 float4
      cp16(As + arow * AS_LD + kc, &A[(size_t)(m0 + arow) * 128 + kb + kc]);
    }
#pragma unroll
    for (int i = 0; i < 4; i++) {
      int c = tid + 256 * i;
      int brow = c >> 5, nc = (c & 31) << 2; // 32 rows x 32 float4
      cp16(Bs + brow * BS_LD + nc, &W[(size_t)(kb + brow) * 384 + n0 + nc]);
    }
    asm volatile("cp.async.commit_group;");
  };

  load_stage(0, 0);

#pragma unroll 1
  for (int it = 0; it < 4; it++) {
    if (it < 3) {
      load_stage((it + 1) & 1, (it + 1) * 32);
      asm volatile("cp.async.wait_group 1;");
    } else {
      asm volatile("cp.async.wait_group 0;");
    }
    __syncthreads();

    const float* As = smem + (it & 1) * AS_FLOATS;
    const float* Bs = smem + 2 * AS_FLOATS + (it & 1) * BS_FLOATS;

#pragma unroll
    for (int ks = 0; ks < 4; ks++) {
      const int kA = ks * 8 + lr4;
      const int kB = kA + 4;
      unsigned int a_hi[2][4], a_lo[2][4];
#pragma unroll
      for (int mf = 0; mf < 2; mf++) {
        const int rb = 32 * wm + 16 * mf + lq;
        float r0 = As[rb * AS_LD + kA];
        float r1 = As[(rb + 8) * AS_LD + kA];
        float r2 = As[rb * AS_LD + kB];
        float r3 = As[(rb + 8) * AS_LD + kB];
        a_hi[mf][0] = f2tf32(r0); a_lo[mf][0] = f2tf32(r0 - __uint_as_float(a_hi[mf][0]));
        a_hi[mf][1] = f2tf32(r1); a_lo[mf][1] = f2tf32(r1 - __uint_as_float(a_hi[mf][1]));
        a_hi[mf][2] = f2tf32(r2); a_lo[mf][2] = f2tf32(r2 - __uint_as_float(a_hi[mf][2]));
        a_hi[mf][3] = f2tf32(r3); a_lo[mf][3] = f2tf32(r3 - __uint_as_float(a_hi[mf][3]));
      }
#pragma unroll
      for (int nf = 0; nf < 8; nf++) {
        const int cb = 64 * wn + 8 * nf + lq;
        float b0 = Bs[kA * BS_LD + cb];
        float b1 = Bs[kB * BS_LD + cb];
        unsigned int bh0 = f2tf32(b0), bl0 = f2tf32(b0 - __uint_as_float(bh0));
        unsigned int bh1 = f2tf32(b1), bl1 = f2tf32(b1 - __uint_as_float(bh1));
#pragma unroll
        for (int mf = 0; mf < 2; mf++) {
          mma_tf32(acc[mf][nf], a_hi[mf][0], a_hi[mf][1], a_hi[mf][2], a_hi[mf][3], bh0, bh1);
          mma_tf32(acc[mf][nf], a_hi[mf][0], a_hi[mf][1], a_hi[mf][2], a_hi[mf][3], bl0, bl1);
          mma_tf32(acc[mf][nf], a_lo[mf][0], a_lo[mf][1], a_lo[mf][2], a_lo[mf][3], bh0, bh1);
        }
      }
    }
    __syncthreads();
  }

  // --- transpose epilogue via smem staging [32][132] (reuses As stage 0) ---
  float* Es = smem;
#pragma unroll 1
  for (int c = 0; c < 4; c++) {
    if (wn == (c >> 1)) {
#pragma unroll
      for (int nfl = 0; nfl < 4; nfl++) {
        const int nf = 4 * (c & 1) + nfl;
#pragma unroll
        for (int mf = 0; mf < 2; mf++)
#pragma unroll
          for (int j = 0; j < 4; j++) {
            int fr = 8 * nfl + 2 * lr4 + (j & 1);
            int ml = 32 * wm + 16 * mf + lq + 8 * (j >> 1);
            Es[fr * 132 + ml] = acc[mf][nf][j];
          }
      }
    }
    __syncthreads();
#pragma unroll
    for (int j4 = 0; j4 < 4; j4++) {
      int fr = (tid >> 5) + 8 * j4;
      int mloc = (tid & 31) * 4;
      int gf = n0 + 32 * c + fr;
#pragma unroll
      for (int e = 0; e < 4; e++) {
        int m = m0 + mloc + e;
        int b = m / NN;
        int n = m - b * NN;
        g_kt[((size_t)b * 384 + gf) * NN + n] = Es[fr * 132 + mloc + e];
      }
    }
    __syncthreads();
  }
}

// ---------------------------------------------------------------------------
// K3: query build (unchanged)
// ---------------------------------------------------------------------------
__global__ __launch_bounds__(128) void query_kernel(
    const float* __restrict__ emb, const float* __restrict__ W_fixed,
    const float* __restrict__ W_step, const int* __restrict__ seq) {
  const int bm = blockIdx.x;
  const int b = bm >> 4;
  const int d = threadIdx.x;
  __shared__ float mean[DD], ef[DD], el[DD];
  float s = 0.f;
#pragma unroll
  for (int c = 0; c < NCHUNK; c++) s += g_fpart[(b * NCHUNK + c) * DD + d];
  mean[d] = s * (1.0f / (float)NN);
  int fidx = seq[bm * 2];
  int lidx = seq[bm * 2 + 1];
  ef[d] = emb[((size_t)b * NN + fidx) * DD + d];
  el[d] = emb[((size_t)b * NN + lidx) * DD + d];
  __syncthreads();
  float a = 0.f;
#pragma unroll 8
  for (int k = 0; k < DD; k++) a = fmaf(mean[k], W_fixed[k * DD + d], a);
#pragma unroll 8
  for (int k = 0; k < DD; k++) a = fmaf(ef[k], W_step[k * DD + d], a);
#pragma unroll 8
  for (int k = 0; k < DD; k++) a = fmaf(el[k], W_step[(DD + k) * DD + d], a);
  g_q[bm * DD + d] = a;
}

// ---------------------------------------------------------------------------
// K4: beam-batched glimpse partials (unchanged)
// ---------------------------------------------------------------------------
__global__ __launch_bounds__(256) void glimpse_kernel() {
  const int b = blockIdx.x, c = blockIdx.y;
  const int n0 = c * CHN;
  const int tid = threadIdx.x;
  const int h = tid >> 5;
  const int lane = tid & 31;

  __shared__ float q_s[BEAM][DD];
  __shared__ unsigned char mk[BEAM][260];
  __shared__ float s_s[HH][BEAM][33];
  __shared__ float v_s[HH][DHH][33];

  for (int i = tid; i < BEAM * DD; i += 256) q_s[i >> 7][i & 127] = g_q[b * BEAM * DD + i];
  for (int i = tid; i < BEAM * 256; i += 256) {
    int m = i >> 8, n = i & 255;
    mk[m][n] = (n < CHN) ? g_mask[((size_t)(b * BEAM + m)) * NN + n0 + n] : (unsigned char)1;
  }
  __syncthreads();

  const float* __restrict__ gk = g_kt + ((size_t)b * 384 + h * DHH) * NN;
  const float* __restrict__ gv = g_kt + ((size_t)b * 384 + 128 + h * DHH) * NN;

  const int mown = lane & 15;
  const int tg = lane >> 4;
  float m_run = -1e30f, s_run = 0.f;
  float acc[8];
#pragma unroll
  for (int j = 0; j < 8; j++) acc[j] = 0.f;

#pragma unroll 1
  for (int g = 0; g < 8; g++) {
    const int nl = g * 32 + lane;
    const bool valid = nl < CHN;
    const int n = n0 + nl;
    float kf[DHH];
#pragma unroll
    for (int t = 0; t < DHH; t++) kf[t] = valid ? gk[(size_t)t * NN + n] : 0.f;
#pragma unroll
    for (int t = 0; t < DHH; t++) v_s[h][t][lane] = valid ? gv[(size_t)t * NN + n] : 0.f;
#pragma unroll
    for (int mi = 0; mi < BEAM; mi++) {
      const float4* qv = (const float4*)&q_s[mi][h * DHH];
      float s = 0.f;
#pragma unroll
      for (int t4 = 0; t4 < 4; t4++) {
        float4 q4 = qv[t4];
        s = fmaf(q4.x, kf[t4 * 4 + 0], s);
        s = fmaf(q4.y, kf[t4 * 4 + 1], s);
        s = fmaf(q4.z, kf[t4 * 4 + 2], s);
        s = fmaf(q4.w, kf[t4 * 4 + 3], s);
      }
      s_s[h][mi][lane] = valid ? s * 0.25f : -1e30f;
    }
    __syncwarp();
    float gm = -1e30f;
#pragma unroll
    for (int j = 0; j < 32; j++) {
      float s = mk[mown][g * 32 + j] ? -1e30f : s_s[h][mown][j];
      s_s[h][mown][j] = s;
      gm = fmaxf(gm, s);
    }
    float mnew = fmaxf(m_run, gm);
    float scale = fexp(m_run - mnew);
    float ssum = 0.f;
#pragma unroll
    for (int j = 0; j < 8; j++) acc[j] *= scale;
#pragma unroll
    for (int j = 0; j < 32; j++) {
      float p = fexp(s_s[h][mown][j] - mnew);
      ssum += p;
#pragma unroll
      for (int jj = 0; jj < 8; jj++) acc[jj] = fmaf(p, v_s[h][tg * 8 + jj][j], acc[jj]);
    }
    s_run = s_run * scale + ssum;
    m_run = mnew;
    __syncwarp();
  }
  const int idx = ((b * NCHUNK + c) * HH + h) * BEAM + mown;
  if (tg == 0) { g_pm[idx] = m_run; g_ps[idx] = s_run; }
#pragma unroll
  for (int j = 0; j < 8; j++) g_pacc[idx * DHH + tg * 8 + j] = acc[j];
}

// ---------------------------------------------------------------------------
// K5: reduce partials -> heads -> glimpse (unchanged)
// ---------------------------------------------------------------------------
__global__ __launch_bounds__(128) void reduce_kernel(const float* __restrict__ W_out) {
  const int bm = blockIdx.x;
  const int b = bm >> 4;
  const int m = bm & 15;
  const int d = threadIdx.x;
  const int h = d >> 4;
  const int t = d & 15;
  __shared__ float heads[DD];
  float M = -1e30f, S = 0.f, A = 0.f;
#pragma unroll
  for (int c = 0; c < NCHUNK; c++) {
    const int idx = ((b * NCHUNK + c) * HH + h) * BEAM + m;
    float mc = g_pm[idx];
    float sc = g_ps[idx];
    float ac = g_pacc[idx * DHH + t];
    float mn = fmaxf(M, mc);
    float e1 = fexp(M - mn);
    float e2 = fexp(mc - mn);
    S = S * e1 + sc * e2;
    A = A * e1 + ac * e2;
    M = mn;
  }
  heads[d] = A / S;
  __syncthreads();
  float a = 0.f;
#pragma unroll 8
  for (int k = 0; k < DD; k++) a = fmaf(heads[k], W_out[k * DD + d], a);
  g_glim[bm * DD + d] = a;
}

// ---------------------------------------------------------------------------
// K6: beam-batched logits (unchanged)
// ---------------------------------------------------------------------------
__global__ __launch_bounds__(256) void logits_kernel(float* __restrict__ out) {
  const int b = blockIdx.x, c = blockIdx.y;
  const int tid = threadIdx.x;
  __shared__ float glim_s[BEAM][DD];
  __shared__ unsigned char mk[BEAM][260];
  for (int i = tid; i < BEAM * DD; i += 256) glim_s[i >> 7][i & 127] = g_glim[b * BEAM * DD + i];
  for (int i = tid; i < BEAM * 256; i += 256) {
    int m = i >> 8, n = i & 255;
    mk[m][n] = (n < CHN) ? g_mask[((size_t)(b * BEAM + m)) * NN + c * CHN + n] : (unsigned char)1;
  }
  __syncthreads();
  if (tid >= CHN) return;
  const int n = c * CHN + tid;
  const float* __restrict__ lk = g_kt + ((size_t)b * 384 + 256) * NN + n;
  float s[BEAM];
#pragma unroll
  for (int m = 0; m < BEAM; m++) s[m] = 0.f;
#pragma unroll 4
  for (int f = 0; f < DD; f += 4) {
    float l0 = lk[(size_t)(f + 0) * NN];
    float l1 = lk[(size_t)(f + 1) * NN];
    float l2 = lk[(size_t)(f + 2) * NN];
    float l3 = lk[(size_t)(f + 3) * NN];
#pragma unroll
    for (int m = 0; m < BEAM; m++) {
      float4 g4 = *(const float4*)&glim_s[m][f];
      s[m] = fmaf(g4.x, l0, s[m]);
      s[m] = fmaf(g4.y, l1, s[m]);
      s[m] = fmaf(g4.z, l2, s[m]);
      s[m] = fmaf(g4.w, l3, s[m]);
    }
  }
  const float invsq = 0.08838834764831845f;
#pragma unroll
  for (int m = 0; m < BEAM; m++) {
    float v = 10.f * tanhf(s[m] * invsq);
    if (mk[m][tid]) v = -FLT_MAX;
    out[((size_t)(b * BEAM + m)) * NN + n] = v;
  }
}

// ---------------------------------------------------------------------------
// K7: finalize per (b,m): log_softmax + top3 (unchanged)
// ---------------------------------------------------------------------------
__global__ __launch_bounds__(256) void finalize_kernel(float* __restrict__ out) {
  const int bm = blockIdx.x;
  const int tid = threadIdx.x;
  float* __restrict__ lp = out + (size_t)bm * NN;
  __shared__ float logits[NN];
  __shared__ float red[256];
  __shared__ float stv[256][3];
  __shared__ int sti[256][3];

  float tv0 = -INFINITY, tv1 = -INFINITY, tv2 = -INFINITY;
  int ti0 = 0, ti1 = 0, ti2 = 0;
  float lmax = -INFINITY;
#pragma unroll 1
  for (int k = 0; k < 8; k++) {
    const int n = tid + 256 * k;
    if (n >= NN) break;
    float v = lp[n];
    logits[n] = v;
    lmax = fmaxf(lmax, v);
    if (v > tv0) { tv2 = tv1; ti2 = ti1; tv1 = tv0; ti1 = ti0; tv0 = v; ti0 = n; }
    else if (v > tv1) { tv2 = tv1; ti2 = ti1; tv1 = v; ti1 = n; }
    else if (v > tv2) { tv2 = v; ti2 = n; }
  }
  stv[tid][0] = tv0; stv[tid][1] = tv1; stv[tid][2] = tv2;
  sti[tid][0] = ti0; sti[tid][1] = ti1; sti[tid][2] = ti2;
  red[tid] = lmax;
  __syncthreads();
  for (int s2 = 128; s2 > 0; s2 >>= 1) {
    if (tid < s2) red[tid] = fmaxf(red[tid], red[tid + s2]);
    __syncthreads();
  }
  lmax = red[0];
  __syncthreads();
  float lsum = 0.f;
  for (int n = tid; n < NN; n += 256) lsum += fexp(logits[n] - lmax);
  red[tid] = lsum;
  __syncthreads();
  for (int s2 = 128; s2 > 0; s2 >>= 1) {
    if (tid < s2) red[tid] += red[tid + s2];
    __syncthreads();
  }
  const float lse = lmax + __logf(red[0]);

  for (int n = tid; n < NN; n += 256) lp[n] = logits[n] - lse;

  for (int s2 = 128; s2 > 0; s2 >>= 1) {
    if (tid < s2) {
      float a0 = stv[tid][0], a1 = stv[tid][1], a2 = stv[tid][2];
      int i0 = sti[tid][0], i1 = sti[tid][1], i2 = sti[tid][2];
#pragma unroll
      for (int j = 0; j < 3; j++) {
        float v = stv[tid + s2][j];
        int ii = sti[tid + s2][j];
        if (v > a0) { a2 = a1; i2 = i1; a1 = a0; i1 = i0; a0 = v; i0 = ii; }
        else if (v > a1) { a2 = a1; i2 = i1; a1 = v; i1 = ii; }
        else if (v > a2) { a2 = v; i2 = ii; }
      }
      stv[tid][0] = a0; stv[tid][1] = a1; stv[tid][2] = a2;
      sti[tid][0] = i0; sti[tid][1] = i1; sti[tid][2] = i2;
    }
    __syncthreads();
  }
  if (tid == 0) {
    float* tvo = out + (size_t)BB * BEAM * NN + bm * 3;
    float* tio = out + (size_t)BB * BEAM * NN + (size_t)BB * BEAM * 3 + bm * 3;
    tvo[0] = stv[0][0] - lse; tvo[1] = stv[0][1] - lse; tvo[2] = stv[0][2] - lse;
    tio[0] = (float)sti[0][0]; tio[1] = (float)sti[0][1]; tio[2] = (float)sti[0][2];
  }
}

// ---------------------------------------------------------------------------
extern "C" void kernel_launch(void* const* d_in, const int* in_sizes, int n_in,
                              void* d_out, int out_size) {
  const float* emb = nullptr;
  const float* W_node = nullptr;
  const float* W_fixed = nullptr;
  const float* W_step = nullptr;
  const float* W_out = nullptr;
  const int* seq = nullptr;
  const unsigned char* mask = nullptr;
  for (int i = 0; i < n_in; i++) {
    int sz = in_sizes[i];
    if (sz == BB * NN * DD) emb = (const float*)d_in[i];
    else if (sz == DD * 3 * DD) W_node = (const float*)d_in[i];
    else if (sz == 2 * DD * DD) W_step = (const float*)d_in[i];
    else if (sz == BB * BEAM * 2) seq = (const int*)d_in[i];
    else if (sz == BB * BEAM * NN) mask = (const unsigned char*)d_in[i];
    else if (sz == DD * DD) {
      if (!W_fixed) W_fixed = (const float*)d_in[i];
      else W_out = (const float*)d_in[i];
    }
  }
  float* out = (float*)d_out;

  static int smem_set = 0;
  if (!smem_set) {
    cudaFuncSetAttribute(kvl_gemm_tf32, cudaFuncAttributeMaxDynamicSharedMemorySize,
                         SMEM_FLOATS * (int)sizeof(float));
    smem_set = 1;
  }

  detect_mask_kernel<<<64, 256>>>(mask);
  convert_mask_kernel<<<(BB * BEAM * NN + 255) / 256, 256>>>(mask);
  fpart_kernel<<<dim3(BB, NCHUNK), 512>>>(emb);
  kvl_gemm_tf32<<<dim3(3, (BB * NN) / 128), 256, SMEM_FLOATS * sizeof(float)>>>(emb, W_node);
  query_kernel<<<BB * BEAM, 128>>>(emb, W_fixed, W_step, seq);
  glimpse_kernel<<<dim3(BB, NCHUNK), 256>>>();
  reduce_kernel<<<BB * BEAM, 128>>>(W_out);
  logits_kernel<<<dim3(BB, NCHUNK), 256>>>(out);
  finalize_kernel<<<BB * BEAM, 256>>>(out);
}

// round 13
// speedup vs baseline: 1.6291x; 1.4367x over previous
#include <cuda_runtime.h>
#include <cstdint>
#include <cfloat>
#include <math.h>

// Problem constants
#define BB 64
#define NN 2000
#define DD 128
#define HH 8
#define DHH 16
#define BEAM 16
#define NCHUNK 8
#define CHN 250

// Scratch
__device__ float g_kt[(size_t)BB * 256 * NN + 64];        // feature-major gk|gv
__device__ float g_et[(size_t)BB * 128 * NN + 64];        // feature-major emb
__device__ float g_Mt[DD * DD];                           // M_T[k][d] = sum_t W_out[k][t] W_l[d][t]
__device__ unsigned char g_mask[(size_t)BB * BEAM * NN];
__device__ int g_isbool;
__device__ float g_fpart[BB * NCHUNK * DD];
__device__ float g_q[BB * BEAM * DD];
__device__ float g_pm[BB * NCHUNK * HH * BEAM];
__device__ float g_ps[BB * NCHUNK * HH * BEAM];
__device__ float g_pacc[BB * NCHUNK * HH * BEAM * DHH];
__device__ float g_glim[BB * BEAM * DD];                  // glim2 vectors

// fma-pipe exp for x <= 0
__device__ __forceinline__ float fexp(float x) {
  x = fmaxf(x, -80.f);
  float y = x * 1.4426950408889634f;
  float r = y + 12582912.f;
  float k = r - 12582912.f;
  float f = y - k;
  float p = 1.5403530393381609e-4f;
  p = fmaf(p, f, 1.3333558146428443e-3f);
  p = fmaf(p, f, 9.6181291976353993e-3f);
  p = fmaf(p, f, 5.5504108664821580e-2f);
  p = fmaf(p, f, 2.4022650695910071e-1f);
  p = fmaf(p, f, 6.9314718055994531e-1f);
  p = fmaf(p, f, 1.0f);
  int e = (int)k;
  return p * __int_as_float((e + 127) << 23);
}

__device__ __forceinline__ void cp16(void* sptr, const void* gptr) {
  unsigned int saddr = (unsigned int)__cvta_generic_to_shared(sptr);
  asm volatile("cp.async.cg.shared.global [%0], [%1], 16;" :: "r"(saddr), "l"(gptr));
}

// ---------------- mask / fpart (validated) ----------------
__global__ __launch_bounds__(256) void detect_mask_kernel(const unsigned char* __restrict__ m) {
  int base = blockIdx.x * (1 << 14);
  int local = 0;
  for (int i = threadIdx.x; i < (1 << 14); i += 256) {
    int idx = base + i;
    if ((idx & 3) && m[idx]) local = 1;
  }
  if (__syncthreads_or(local)) {
    if (threadIdx.x == 0) g_isbool = 1;
  }
}

__global__ __launch_bounds__(256) void convert_mask_kernel(const unsigned char* __restrict__ m) {
  int i = blockIdx.x * 256 + threadIdx.x;
  if (i >= BB * BEAM * NN) return;
  if (g_isbool) g_mask[i] = (m[i] != 0);
  else g_mask[i] = (((const int*)m)[i] != 0);
}

__global__ __launch_bounds__(512) void fpart_kernel(const float* __restrict__ emb) {
  int b = blockIdx.x, c = blockIdx.y;
  int r = threadIdx.x >> 7, d = threadIdx.x & 127;
  __shared__ float part[4][DD];
  const float* p = emb + ((size_t)b * NN + c * CHN) * DD + d;
  float s = 0.f;
#pragma unroll 4
  for (int n = r; n < CHN; n += 4) s += p[(size_t)n * DD];
  part[r][d] = s;
  __syncthreads();
  if (r == 0)
    g_fpart[(b * NCHUNK + c) * DD + d] = part[0][d] + part[1][d] + part[2][d] + part[3][d];
}

// ---------------------------------------------------------------------------
// Transpose emb -> g_et[b][d][n]. grid (63, 4, 64), block (32, 8).
// ---------------------------------------------------------------------------
__global__ __launch_bounds__(256) void etrans_kernel(const float* __restrict__ emb) {
  __shared__ float t[32][33];
  const int n0 = blockIdx.x * 32, d0 = blockIdx.y * 32, b = blockIdx.z;
  const int tx = threadIdx.x, ty = threadIdx.y;
#pragma unroll
  for (int r = 0; r < 4; r++) {
    int n = n0 + ty + 8 * r;
    if (n < NN) t[ty + 8 * r][tx] = emb[((size_t)b * NN + n) * DD + d0 + tx];
  }
  __syncthreads();
#pragma unroll
  for (int r = 0; r < 4; r++) {
    int n = n0 + tx;
    int d = d0 + ty + 8 * r;
    if (n < NN) g_et[((size_t)b * DD + d) * NN + n] = t[tx][ty + 8 * r];
  }
}

// ---------------------------------------------------------------------------
// M_T[k][d] = sum_t W_out[k][t] * W_l[d][t], W_l[d][t] = W_node[d*384+256+t]
// ---------------------------------------------------------------------------
__global__ __launch_bounds__(256) void mt_kernel(const float* __restrict__ W_node,
                                                 const float* __restrict__ W_out) {
  int idx = blockIdx.x * 256 + threadIdx.x;
  int k = idx >> 7, d = idx & 127;
  const float* wo = W_out + k * DD;
  const float* wl = W_node + (size_t)d * 384 + 256;
  float s = 0.f;
#pragma unroll 8
  for (int t = 0; t < DD; t++) s = fmaf(wo[t], wl[t], s);
  g_Mt[k * DD + d] = s;
}

// ---------------------------------------------------------------------------
// K2: [gk|gv] = emb[128000,128] @ W_node[:,0:256], fp32 SIMT, cp.async B +
// reg-prefetched A, double buffered. Tile 128m x 128f, BK=32, 8x8 microtile.
// grid (2, 1000), 256 threads, 2 CTAs/SM. Output feature-major to g_kt.
// ---------------------------------------------------------------------------
#define TS 4224  // 32*132 floats per stage
__global__ __launch_bounds__(256, 2) void kvl_gemm(
    const float* __restrict__ A, const float* __restrict__ W) {
  extern __shared__ float smem[];  // As[2][32][132] | Bs[2][32][132]
  float* Bs_base = smem + 2 * TS;
  const int m0 = blockIdx.y * 128;
  const int n0 = blockIdx.x * 128;
  const int tid = threadIdx.x;
  const int tx = tid & 15;
  const int ty = tid >> 4;
  const int lrA = tid >> 3;        // 0..31
  const int lcA = (tid & 7) * 4;   // k float4 offset
  const int wrB = tid >> 5;        // 0..7
  const int wcB = (tid & 31) * 4;  // n float4 offset

  float acc[8][8];
#pragma unroll
  for (int i = 0; i < 8; i++)
#pragma unroll
    for (int j = 0; j < 8; j++) acc[i][j] = 0.f;

  auto cp_b = [&](int st, int kb) {
#pragma unroll
    for (int p = 0; p < 4; p++) {
      int kr = wrB + 8 * p;
      cp16(&Bs_base[st * TS + kr * 132 + wcB], &W[(size_t)(kb + kr) * 384 + n0 + wcB]);
    }
    asm volatile("cp.async.commit_group;");
  };
  auto ldg_a = [&](int kb, float4* r) {
#pragma unroll
    for (int p = 0; p < 4; p++)
      r[p] = *(const float4*)&A[(size_t)(m0 + lrA + 32 * p) * 128 + kb + lcA];
  };
  auto sts_a = [&](int st, const float4* r) {
#pragma unroll
    for (int p = 0; p < 4; p++) {
      int row = lrA + 32 * p;
      smem[st * TS + (lcA + 0) * 132 + row] = r[p].x;
      smem[st * TS + (lcA + 1) * 132 + row] = r[p].y;
      smem[st * TS + (lcA + 2) * 132 + row] = r[p].z;
      smem[st * TS + (lcA + 3) * 132 + row] = r[p].w;
    }
  };

  float4 areg[4];
  cp_b(0, 0);
  ldg_a(0, areg);
  sts_a(0, areg);

#pragma unroll 1
  for (int it = 0; it < 4; it++) {
    if (it < 3) {
      cp_b((it + 1) & 1, (it + 1) * 32);
      ldg_a((it + 1) * 32, areg);
      asm volatile("cp.async.wait_group 1;");
    } else {
      asm volatile("cp.async.wait_group 0;");
    }
    __syncthreads();
    const float* As = smem + (it & 1) * TS;
    const float* Bs = Bs_base + (it & 1) * TS;
#pragma unroll 8
    for (int k = 0; k < 32; k++) {
      float a[8], bf[8];
      *(float4*)&a[0] = *(const float4*)&As[k * 132 + ty * 8];
      *(float4*)&a[4] = *(const float4*)&As[k * 132 + ty * 8 + 4];
      *(float4*)&bf[0] = *(const float4*)&Bs[k * 132 + tx * 8];
      *(float4*)&bf[4] = *(const float4*)&Bs[k * 132 + tx * 8 + 4];
#pragma unroll
      for (int i = 0; i < 8; i++)
#pragma unroll
        for (int j = 0; j < 8; j++) acc[i][j] = fmaf(a[i], bf[j], acc[i][j]);
    }
    if (it < 3) sts_a((it + 1) & 1, areg);
    __syncthreads();
  }

  // --- transpose epilogue (validated): 4 chunks of 32 feature-rows ---
  float* Es = smem;
#pragma unroll 1
  for (int c = 0; c < 4; c++) {
    if ((tx >> 2) == c) {
#pragma unroll
      for (int i = 0; i < 8; i++)
#pragma unroll
        for (int j = 0; j < 8; j++)
          Es[((tx - 4 * c) * 8 + j) * 132 + ty * 8 + i] = acc[i][j];
    }
    __syncthreads();
#pragma unroll
    for (int j4 = 0; j4 < 4; j4++) {
      int fr = (tid >> 5) + 8 * j4;
      int mloc = (tid & 31) * 4;
      int gf = n0 + 32 * c + fr;
#pragma unroll
      for (int e = 0; e < 4; e++) {
        int m = m0 + mloc + e;
        int b = m / NN;
        int n = m - b * NN;
        g_kt[((size_t)b * 256 + gf) * NN + n] = Es[fr * 132 + mloc + e];
      }
    }
    __syncthreads();
  }
}

// ---------------------------------------------------------------------------
// K3: query build (unchanged)
// ---------------------------------------------------------------------------
__global__ __launch_bounds__(128) void query_kernel(
    const float* __restrict__ emb, const float* __restrict__ W_fixed,
    const float* __restrict__ W_step, const int* __restrict__ seq) {
  const int bm = blockIdx.x;
  const int b = bm >> 4;
  const int d = threadIdx.x;
  __shared__ float mean[DD], ef[DD], el[DD];
  float s = 0.f;
#pragma unroll
  for (int c = 0; c < NCHUNK; c++) s += g_fpart[(b * NCHUNK + c) * DD + d];
  mean[d] = s * (1.0f / (float)NN);
  int fidx = seq[bm * 2];
  int lidx = seq[bm * 2 + 1];
  ef[d] = emb[((size_t)b * NN + fidx) * DD + d];
  el[d] = emb[((size_t)b * NN + lidx) * DD + d];
  __syncthreads();
  float a = 0.f;
#pragma unroll 8
  for (int k = 0; k < DD; k++) a = fmaf(mean[k], W_fixed[k * DD + d], a);
#pragma unroll 8
  for (int k = 0; k < DD; k++) a = fmaf(ef[k], W_step[k * DD + d], a);
#pragma unroll 8
  for (int k = 0; k < DD; k++) a = fmaf(el[k], W_step[(DD + k) * DD + d], a);
  g_q[bm * DD + d] = a;
}

// ---------------------------------------------------------------------------
// K4: beam-batched glimpse partials (g_kt 256-stride)
// ---------------------------------------------------------------------------
__global__ __launch_bounds__(256) void glimpse_kernel() {
  const int b = blockIdx.x, c = blockIdx.y;
  const int n0 = c * CHN;
  const int tid = threadIdx.x;
  const int h = tid >> 5;
  const int lane = tid & 31;

  __shared__ float q_s[BEAM][DD];
  __shared__ unsigned char mk[BEAM][260];
  __shared__ float s_s[HH][BEAM][33];
  __shared__ float v_s[HH][DHH][33];

  for (int i = tid; i < BEAM * DD; i += 256) q_s[i >> 7][i & 127] = g_q[b * BEAM * DD + i];
  for (int i = tid; i < BEAM * 256; i += 256) {
    int m = i >> 8, n = i & 255;
    mk[m][n] = (n < CHN) ? g_mask[((size_t)(b * BEAM + m)) * NN + n0 + n] : (unsigned char)1;
  }
  __syncthreads();

  const float* __restrict__ gk = g_kt + ((size_t)b * 256 + h * DHH) * NN;
  const float* __restrict__ gv = g_kt + ((size_t)b * 256 + 128 + h * DHH) * NN;

  const int mown = lane & 15;
  const int tg = lane >> 4;
  float m_run = -1e30f, s_run = 0.f;
  float acc[8];
#pragma unroll
  for (int j = 0; j < 8; j++) acc[j] = 0.f;

#pragma unroll 1
  for (int g = 0; g < 8; g++) {
    const int nl = g * 32 + lane;
    const bool valid = nl < CHN;
    const int n = n0 + nl;
    float kf[DHH];
#pragma unroll
    for (int t = 0; t < DHH; t++) kf[t] = valid ? gk[(size_t)t * NN + n] : 0.f;
#pragma unroll
    for (int t = 0; t < DHH; t++) v_s[h][t][lane] = valid ? gv[(size_t)t * NN + n] : 0.f;
#pragma unroll
    for (int mi = 0; mi < BEAM; mi++) {
      const float4* qv = (const float4*)&q_s[mi][h * DHH];
      float s = 0.f;
#pragma unroll
      for (int t4 = 0; t4 < 4; t4++) {
        float4 q4 = qv[t4];
        s = fmaf(q4.x, kf[t4 * 4 + 0], s);
        s = fmaf(q4.y, kf[t4 * 4 + 1], s);
        s = fmaf(q4.z, kf[t4 * 4 + 2], s);
        s = fmaf(q4.w, kf[t4 * 4 + 3], s);
      }
      s_s[h][mi][lane] = valid ? s * 0.25f : -1e30f;
    }
    __syncwarp();
    float gm = -1e30f;
#pragma unroll
    for (int j = 0; j < 32; j++) {
      float s = mk[mown][g * 32 + j] ? -1e30f : s_s[h][mown][j];
      s_s[h][mown][j] = s;
      gm = fmaxf(gm, s);
    }
    float mnew = fmaxf(m_run, gm);
    float scale = fexp(m_run - mnew);
    float ssum = 0.f;
#pragma unroll
    for (int j = 0; j < 8; j++) acc[j] *= scale;
#pragma unroll
    for (int j = 0; j < 32; j++) {
      float p = fexp(s_s[h][mown][j] - mnew);
      ssum += p;
#pragma unroll
      for (int jj = 0; jj < 8; jj++) acc[jj] = fmaf(p, v_s[h][tg * 8 + jj][j], acc[jj]);
    }
    s_run = s_run * scale + ssum;
    m_run = mnew;
    __syncwarp();
  }
  const int idx = ((b * NCHUNK + c) * HH + h) * BEAM + mown;
  if (tg == 0) { g_pm[idx] = m_run; g_ps[idx] = s_run; }
#pragma unroll
  for (int j = 0; j < 8; j++) g_pacc[idx * DHH + tg * 8 + j] = acc[j];
}

// ---------------------------------------------------------------------------
// K5: reduce partials -> heads -> glim2 = heads @ M_T
// ---------------------------------------------------------------------------
__global__ __launch_bounds__(128) void reduce_kernel() {
  const int bm = blockIdx.x;
  const int b = bm >> 4;
  const int m = bm & 15;
  const int d = threadIdx.x;
  const int h = d >> 4;
  const int t = d & 15;
  __shared__ float heads[DD];
  float M = -1e30f, S = 0.f, A = 0.f;
#pragma unroll
  for (int c = 0; c < NCHUNK; c++) {
    const int idx = ((b * NCHUNK + c) * HH + h) * BEAM + m;
    float mc = g_pm[idx];
    float sc = g_ps[idx];
    float ac = g_pacc[idx * DHH + t];
    float mn = fmaxf(M, mc);
    float e1 = fexp(M - mn);
    float e2 = fexp(mc - mn);
    S = S * e1 + sc * e2;
    A = A * e1 + ac * e2;
    M = mn;
  }
  heads[d] = A / S;
  __syncthreads();
  float a = 0.f;
#pragma unroll 8
  for (int k = 0; k < DD; k++) a = fmaf(heads[k], g_Mt[k * DD + d], a);
  g_glim[bm * DD + d] = a;
}

// ---------------------------------------------------------------------------
// K6: beam-batched logits vs transposed emb (g_et)
// ---------------------------------------------------------------------------
__global__ __launch_bounds__(256) void logits_kernel(float* __restrict__ out) {
  const int b = blockIdx.x, c = blockIdx.y;
  const int tid = threadIdx.x;
  __shared__ float glim_s[BEAM][DD];
  __shared__ unsigned char mk[BEAM][260];
  for (int i = tid; i < BEAM * DD; i += 256) glim_s[i >> 7][i & 127] = g_glim[b * BEAM * DD + i];
  for (int i = tid; i < BEAM * 256; i += 256) {
    int m = i >> 8, n = i & 255;
    mk[m][n] = (n < CHN) ? g_mask[((size_t)(b * BEAM + m)) * NN + c * CHN + n] : (unsigned char)1;
  }
  __syncthreads();
  if (tid >= CHN) return;
  const int n = c * CHN + tid;
  const float* __restrict__ lk = g_et + (size_t)b * DD * NN + n;
  float s[BEAM];
#pragma unroll
  for (int m = 0; m < BEAM; m++) s[m] = 0.f;
#pragma unroll 4
  for (int f = 0; f < DD; f += 4) {
    float l0 = lk[(size_t)(f + 0) * NN];
    float l1 = lk[(size_t)(f + 1) * NN];
    float l2 = lk[(size_t)(f + 2) * NN];
    float l3 = lk[(size_t)(f + 3) * NN];
#pragma unroll
    for (int m = 0; m < BEAM; m++) {
      float4 g4 = *(const float4*)&glim_s[m][f];
      s[m] = fmaf(g4.x, l0, s[m]);
      s[m] = fmaf(g4.y, l1, s[m]);
      s[m] = fmaf(g4.z, l2, s[m]);
      s[m] = fmaf(g4.w, l3, s[m]);
    }
  }
  const float invsq = 0.08838834764831845f;
#pragma unroll
  for (int m = 0; m < BEAM; m++) {
    float v = 10.f * tanhf(s[m] * invsq);
    if (mk[m][tid]) v = -FLT_MAX;
    out[((size_t)(b * BEAM + m)) * NN + n] = v;
  }
}

// ---------------------------------------------------------------------------
// K7: finalize per (b,m): log_softmax + top3 (unchanged)
// ---------------------------------------------------------------------------
__global__ __launch_bounds__(256) void finalize_kernel(float* __restrict__ out) {
  const int bm = blockIdx.x;
  const int tid = threadIdx.x;
  float* __restrict__ lp = out + (size_t)bm * NN;
  __shared__ float logits[NN];
  __shared__ float red[256];
  __shared__ float stv[256][3];
  __shared__ int sti[256][3];

  float tv0 = -INFINITY, tv1 = -INFINITY, tv2 = -INFINITY;
  int ti0 = 0, ti1 = 0, ti2 = 0;
  float lmax = -INFINITY;
#pragma unroll 1
  for (int k = 0; k < 8; k++) {
    const int n = tid + 256 * k;
    if (n >= NN) break;
    float v = lp[n];
    logits[n] = v;
    lmax = fmaxf(lmax, v);
    if (v > tv0) { tv2 = tv1; ti2 = ti1; tv1 = tv0; ti1 = ti0; tv0 = v; ti0 = n; }
    else if (v > tv1) { tv2 = tv1; ti2 = ti1; tv1 = v; ti1 = n; }
    else if (v > tv2) { tv2 = v; ti2 = n; }
  }
  stv[tid][0] = tv0; stv[tid][1] = tv1; stv[tid][2] = tv2;
  sti[tid][0] = ti0; sti[tid][1] = ti1; sti[tid][2] = ti2;
  red[tid] = lmax;
  __syncthreads();
  for (int s2 = 128; s2 > 0; s2 >>= 1) {
    if (tid < s2) red[tid] = fmaxf(red[tid], red[tid + s2]);
    __syncthreads();
  }
  lmax = red[0];
  __syncthreads();
  float lsum = 0.f;
  for (int n = tid; n < NN; n += 256) lsum += fexp(logits[n] - lmax);
  red[tid] = lsum;
  __syncthreads();
  for (int s2 = 128; s2 > 0; s2 >>= 1) {
    if (tid < s2) red[tid] += red[tid + s2];
    __syncthreads();
  }
  const float lse = lmax + __logf(red[0]);

  for (int n = tid; n < NN; n += 256) lp[n] = logits[n] - lse;

  for (int s2 = 128; s2 > 0; s2 >>= 1) {
    if (tid < s2) {
      float a0 = stv[tid][0], a1 = stv[tid][1], a2 = stv[tid][2];
      int i0 = sti[tid][0], i1 = sti[tid][1], i2 = sti[tid][2];
#pragma unroll
      for (int j = 0; j < 3; j++) {
        float v = stv[tid + s2][j];
        int ii = sti[tid + s2][j];
        if (v > a0) { a2 = a1; i2 = i1; a1 = a0; i1 = i0; a0 = v; i0 = ii; }
        else if (v > a1) { a2 = a1; i2 = i1; a1 = v; i1 = ii; }
        else if (v > a2) { a2 = v; i2 = ii; }
      }
      stv[tid][0] = a0; stv[tid][1] = a1; stv[tid][2] = a2;
      sti[tid][0] = i0; sti[tid][1] = i1; sti[tid][2] = i2;
    }
    __syncthreads();
  }
  if (tid == 0) {
    float* tvo = out + (size_t)BB * BEAM * NN + bm * 3;
    float* tio = out + (size_t)BB * BEAM * NN + (size_t)BB * BEAM * 3 + bm * 3;
    tvo[0] = stv[0][0] - lse; tvo[1] = stv[0][1] - lse; tvo[2] = stv[0][2] - lse;
    tio[0] = (float)sti[0][0]; tio[1] = (float)sti[0][1]; tio[2] = (float)sti[0][2];
  }
}

// ---------------------------------------------------------------------------
extern "C" void kernel_launch(void* const* d_in, const int* in_sizes, int n_in,
                              void* d_out, int out_size) {
  const float* emb = nullptr;
  const float* W_node = nullptr;
  const float* W_fixed = nullptr;
  const float* W_step = nullptr;
  const float* W_out = nullptr;
  const int* seq = nullptr;
  const unsigned char* mask = nullptr;
  for (int i = 0; i < n_in; i++) {
    int sz = in_sizes[i];
    if (sz == BB * NN * DD) emb = (const float*)d_in[i];
    else if (sz == DD * 3 * DD) W_node = (const float*)d_in[i];
    else if (sz == 2 * DD * DD) W_step = (const float*)d_in[i];
    else if (sz == BB * BEAM * 2) seq = (const int*)d_in[i];
    else if (sz == BB * BEAM * NN) mask = (const unsigned char*)d_in[i];
    else if (sz == DD * DD) {
      if (!W_fixed) W_fixed = (const float*)d_in[i];
      else W_out = (const float*)d_in[i];
    }
  }
  float* out = (float*)d_out;

  static int smem_set = 0;
  if (!smem_set) {
    cudaFuncSetAttribute(kvl_gemm, cudaFuncAttributeMaxDynamicSharedMemorySize,
                         4 * TS * (int)sizeof(float));
    smem_set = 1;
  }

  detect_mask_kernel<<<64, 256>>>(mask);
  convert_mask_kernel<<<(BB * BEAM * NN + 255) / 256, 256>>>(mask);
  fpart_kernel<<<dim3(BB, NCHUNK), 512>>>(emb);
  kvl_gemm<<<dim3(2, (BB * NN) / 128), 256, 4 * TS * sizeof(float)>>>(emb, W_node);
  etrans_kernel<<<dim3(63, 4, BB), dim3(32, 8)>>>(emb);
  mt_kernel<<<64, 256>>>(W_node, W_out);
  query_kernel<<<BB * BEAM, 128>>>(emb, W_fixed, W_step, seq);
  glimpse_kernel<<<dim3(BB, NCHUNK), 256>>>();
  reduce_kernel<<<BB * BEAM, 128>>>();
  logits_kernel<<<dim3(BB, NCHUNK), 256>>>(out);
  finalize_kernel<<<BB * BEAM, 256>>>(out);
}

// round 16
// speedup vs baseline: 1.7109x; 1.0502x over previous
#include <cuda_runtime.h>
#include <cstdint>
#include <cfloat>
#include <math.h>

// Problem constants
#define BB 64
#define NN 2000
#define DD 128
#define HH 8
#define DHH 16
#define BEAM 16
#define NCHUNK 8
#define CHN 250

// Scratch
__device__ float g_kt[(size_t)BB * 256 * NN + 64];        // feature-major gk|gv
__device__ float g_et[(size_t)BB * 128 * NN + 64];        // feature-major emb
__device__ float g_Mt[DD * DD];                           // M_T[k][d]
__device__ int g_isbool;
__device__ float g_fpart[BB * NCHUNK * DD];
__device__ float g_q[BB * BEAM * DD];
__device__ float g_pm[BB * NCHUNK * HH * BEAM];
__device__ float g_ps[BB * NCHUNK * HH * BEAM];
__device__ float g_pacc[BB * NCHUNK * HH * BEAM * DHH];
__device__ float g_glim[BB * BEAM * DD];

// fma-pipe exp for x <= 0
__device__ __forceinline__ float fexp(float x) {
  x = fmaxf(x, -80.f);
  float y = x * 1.4426950408889634f;
  float r = y + 12582912.f;
  float k = r - 12582912.f;
  float f = y - k;
  float p = 1.5403530393381609e-4f;
  p = fmaf(p, f, 1.3333558146428443e-3f);
  p = fmaf(p, f, 9.6181291976353993e-3f);
  p = fmaf(p, f, 5.5504108664821580e-2f);
  p = fmaf(p, f, 2.4022650695910071e-1f);
  p = fmaf(p, f, 6.9314718055994531e-1f);
  p = fmaf(p, f, 1.0f);
  int e = (int)k;
  return p * __int_as_float((e + 127) << 23);
}

__device__ __forceinline__ void cp16(void* sptr, const void* gptr) {
  unsigned int saddr = (unsigned int)__cvta_generic_to_shared(sptr);
  asm volatile("cp.async.cg.shared.global [%0], [%1], 16;" :: "r"(saddr), "l"(gptr));
}

// packed fp32x2 FMA (Blackwell): c = a*b + c elementwise on 2 floats
__device__ __forceinline__ void ffma2(unsigned long long& c, unsigned long long a,
                                      unsigned long long b) {
  asm("fma.rn.f32x2 %0, %1, %2, %0;" : "+l"(c) : "l"(a), "l"(b));
}
__device__ __forceinline__ unsigned long long pack2(float lo, float hi) {
  unsigned long long r;
  asm("mov.b64 %0, {%1, %2};" : "=l"(r) : "f"(lo), "f"(hi));
  return r;
}
__device__ __forceinline__ void unpack2(unsigned long long v, float& lo, float& hi) {
  asm("mov.b64 {%0, %1}, %2;" : "=f"(lo), "=f"(hi) : "l"(v));
}

// mask element read (handles bool-byte or int32 encodings)
__device__ __forceinline__ unsigned char mask_at(const unsigned char* m, size_t idx) {
  if (g_isbool) return (unsigned char)(m[idx] != 0);
  return (unsigned char)(((const int*)m)[idx] != 0);
}

// ---------------- mask detect / fpart ----------------
__global__ __launch_bounds__(256) void detect_mask_kernel(const unsigned char* __restrict__ m) {
  int base = blockIdx.x * (1 << 14);
  int local = 0;
  for (int i = threadIdx.x; i < (1 << 14); i += 256) {
    int idx = base + i;
    if ((idx & 3) && m[idx]) local = 1;
  }
  if (__syncthreads_or(local)) {
    if (threadIdx.x == 0) g_isbool = 1;
  }
}

__global__ __launch_bounds__(512) void fpart_kernel(const float* __restrict__ emb) {
  int b = blockIdx.x, c = blockIdx.y;
  int r = threadIdx.x >> 7, d = threadIdx.x & 127;
  __shared__ float part[4][DD];
  const float* p = emb + ((size_t)b * NN + c * CHN) * DD + d;
  float s = 0.f;
#pragma unroll 4
  for (int n = r; n < CHN; n += 4) s += p[(size_t)n * DD];
  part[r][d] = s;
  __syncthreads();
  if (r == 0)
    g_fpart[(b * NCHUNK + c) * DD + d] = part[0][d] + part[1][d] + part[2][d] + part[3][d];
}

// ---------------------------------------------------------------------------
// Transpose emb -> g_et[b][d][n]. grid (63, 4, 64), block (32, 8).
// ---------------------------------------------------------------------------
__global__ __launch_bounds__(256) void etrans_kernel(const float* __restrict__ emb) {
  __shared__ float t[32][33];
  const int n0 = blockIdx.x * 32, d0 = blockIdx.y * 32, b = blockIdx.z;
  const int tx = threadIdx.x, ty = threadIdx.y;
#pragma unroll
  for (int r = 0; r < 4; r++) {
    int n = n0 + ty + 8 * r;
    if (n < NN) t[ty + 8 * r][tx] = emb[((size_t)b * NN + n) * DD + d0 + tx];
  }
  __syncthreads();
#pragma unroll
  for (int r = 0; r < 4; r++) {
    int n = n0 + tx;
    int d = d0 + ty + 8 * r;
    if (n < NN) g_et[((size_t)b * DD + d) * NN + n] = t[tx][ty + 8 * r];
  }
}

// ---------------------------------------------------------------------------
// M_T[k][d] = sum_t W_out[k][t] * W_node[d*384+256+t]
// ---------------------------------------------------------------------------
__global__ __launch_bounds__(256) void mt_kernel(const float* __restrict__ W_node,
                                                 const float* __restrict__ W_out) {
  int idx = blockIdx.x * 256 + threadIdx.x;
  int k = idx >> 7, d = idx & 127;
  const float* wo = W_out + k * DD;
  const float* wl = W_node + (size_t)d * 384 + 256;
  float s = 0.f;
#pragma unroll 8
  for (int t = 0; t < DD; t++) s = fmaf(wo[t], wl[t], s);
  g_Mt[k * DD + d] = s;
}

// ---------------------------------------------------------------------------
// K2: [gk|gv] = emb @ W_node[:,0:256] via packed f32x2 FMA.
// grid (2, 1000), 256 threads, 2 CTAs/SM.
// ---------------------------------------------------------------------------
#define TS 4224  // 32*132 floats per stage
__global__ __launch_bounds__(256, 2) void kvl_gemm(
    const float* __restrict__ A, const float* __restrict__ W) {
  extern __shared__ float smem[];  // As[2][32][132] | Bs[2][32][132]
  float* Bs_base = smem + 2 * TS;
  const int m0 = blockIdx.y * 128;
  const int n0 = blockIdx.x * 128;
  const int tid = threadIdx.x;
  const int tx = tid & 15;
  const int ty = tid >> 4;
  const int lrA = tid >> 3;
  const int lcA = (tid & 7) * 4;
  const int wrB = tid >> 5;
  const int wcB = (tid & 31) * 4;

  unsigned long long acc2[8][4];
#pragma unroll
  for (int i = 0; i < 8; i++)
#pragma unroll
    for (int jp = 0; jp < 4; jp++) acc2[i][jp] = 0ull;

  auto cp_b = [&](int st, int kb) {
#pragma unroll
    for (int p = 0; p < 4; p++) {
      int kr = wrB + 8 * p;
      cp16(&Bs_base[st * TS + kr * 132 + wcB], &W[(size_t)(kb + kr) * 384 + n0 + wcB]);
    }
    asm volatile("cp.async.commit_group;");
  };
  auto ldg_a = [&](int kb, float4* r) {
#pragma unroll
    for (int p = 0; p < 4; p++)
      r[p] = *(const float4*)&A[(size_t)(m0 + lrA + 32 * p) * 128 + kb + lcA];
  };
  auto sts_a = [&](int st, const float4* r) {
#pragma unroll
    for (int p = 0; p < 4; p++) {
      int row = lrA + 32 * p;
      smem[st * TS + (lcA + 0) * 132 + row] = r[p].x;
      smem[st * TS + (lcA + 1) * 132 + row] = r[p].y;
      smem[st * TS + (lcA + 2) * 132 + row] = r[p].z;
      smem[st * TS + (lcA + 3) * 132 + row] = r[p].w;
    }
  };

  float4 areg[4];
  cp_b(0, 0);
  ldg_a(0, areg);
  sts_a(0, areg);

#pragma unroll 1
  for (int it = 0; it < 4; it++) {
    if (it < 3) {
      cp_b((it + 1) & 1, (it + 1) * 32);
      ldg_a((it + 1) * 32, areg);
      asm volatile("cp.async.wait_group 1;");
    } else {
      asm volatile("cp.async.wait_group 0;");
    }
    __syncthreads();
    const float* As = smem + (it & 1) * TS;
    const float* Bs = Bs_base + (it & 1) * TS;
#pragma unroll 8
    for (int k = 0; k < 32; k++) {
      float a[8], bf[8];
      *(float4*)&a[0] = *(const float4*)&As[k * 132 + ty * 8];
      *(float4*)&a[4] = *(const float4*)&As[k * 132 + ty * 8 + 4];
      *(float4*)&bf[0] = *(const float4*)&Bs[k * 132 + tx * 8];
      *(float4*)&bf[4] = *(const float4*)&Bs[k * 132 + tx * 8 + 4];
      unsigned long long b2[4];
#pragma unroll
      for (int jp = 0; jp < 4; jp++) b2[jp] = pack2(bf[2 * jp], bf[2 * jp + 1]);
#pragma unroll
      for (int i = 0; i < 8; i++) {
        unsigned long long a2 = pack2(a[i], a[i]);
#pragma unroll
        for (int jp = 0; jp < 4; jp++) ffma2(acc2[i][jp], a2, b2[jp]);
      }
    }
    if (it < 3) sts_a((it + 1) & 1, areg);
    __syncthreads();
  }

  // unpack accumulators
  float acc[8][8];
#pragma unroll
  for (int i = 0; i < 8; i++)
#pragma unroll
    for (int jp = 0; jp < 4; jp++) unpack2(acc2[i][jp], acc[i][2 * jp], acc[i][2 * jp + 1]);

  // --- transpose epilogue (validated) ---
  float* Es = smem;
#pragma unroll 1
  for (int c = 0; c < 4; c++) {
    if ((tx >> 2) == c) {
#pragma unroll
      for (int i = 0; i < 8; i++)
#pragma unroll
        for (int j = 0; j < 8; j++)
          Es[((tx - 4 * c) * 8 + j) * 132 + ty * 8 + i] = acc[i][j];
    }
    __syncthreads();
#pragma unroll
    for (int j4 = 0; j4 < 4; j4++) {
      int fr = (tid >> 5) + 8 * j4;
      int mloc = (tid & 31) * 4;
      int gf = n0 + 32 * c + fr;
#pragma unroll
      for (int e = 0; e < 4; e++) {
        int m = m0 + mloc + e;
        int b = m / NN;
        int n = m - b * NN;
        g_kt[((size_t)b * 256 + gf) * NN + n] = Es[fr * 132 + mloc + e];
      }
    }
    __syncthreads();
  }
}

// ---------------------------------------------------------------------------
// K3: query build
// ---------------------------------------------------------------------------
__global__ __launch_bounds__(128) void query_kernel(
    const float* __restrict__ emb, const float* __restrict__ W_fixed,
    const float* __restrict__ W_step, const int* __restrict__ seq) {
  const int bm = blockIdx.x;
  const int b = bm >> 4;
  const int d = threadIdx.x;
  __shared__ float mean[DD], ef[DD], el[DD];
  float s = 0.f;
#pragma unroll
  for (int c = 0; c < NCHUNK; c++) s += g_fpart[(b * NCHUNK + c) * DD + d];
  mean[d] = s * (1.0f / (float)NN);
  int fidx = seq[bm * 2];
  int lidx = seq[bm * 2 + 1];
  ef[d] = emb[((size_t)b * NN + fidx) * DD + d];
  el[d] = emb[((size_t)b * NN + lidx) * DD + d];
  __syncthreads();
  float a = 0.f;
#pragma unroll 8
  for (int k = 0; k < DD; k++) a = fmaf(mean[k], W_fixed[k * DD + d], a);
#pragma unroll 8
  for (int k = 0; k < DD; k++) a = fmaf(ef[k], W_step[k * DD + d], a);
#pragma unroll 8
  for (int k = 0; k < DD; k++) a = fmaf(el[k], W_step[(DD + k) * DD + d], a);
  g_q[bm * DD + d] = a;
}

// ---------------------------------------------------------------------------
// K4: beam-batched glimpse partials (raw mask read)
// ---------------------------------------------------------------------------
__global__ __launch_bounds__(256) void glimpse_kernel(const unsigned char* __restrict__ mask) {
  const int b = blockIdx.x, c = blockIdx.y;
  const int n0 = c * CHN;
  const int tid = threadIdx.x;
  const int h = tid >> 5;
  const int lane = tid & 31;

  __shared__ float q_s[BEAM][DD];
  __shared__ unsigned char mk[BEAM][260];
  __shared__ float s_s[HH][BEAM][33];
  __shared__ float v_s[HH][DHH][33];

  for (int i = tid; i < BEAM * DD; i += 256) q_s[i >> 7][i & 127] = g_q[b * BEAM * DD + i];
  for (int i = tid; i < BEAM * 256; i += 256) {
    int m = i >> 8, n = i & 255;
    mk[m][n] = (n < CHN) ? mask_at(mask, (size_t)(b * BEAM + m) * NN + n0 + n) : (unsigned char)1;
  }
  __syncthreads();

  const float* __restrict__ gk = g_kt + ((size_t)b * 256 + h * DHH) * NN;
  const float* __restrict__ gv = g_kt + ((size_t)b * 256 + 128 + h * DHH) * NN;

  const int mown = lane & 15;
  const int tg = lane >> 4;
  float m_run = -1e30f, s_run = 0.f;
  float acc[8];
#pragma unroll
  for (int j = 0; j < 8; j++) acc[j] = 0.f;

#pragma unroll 1
  for (int g = 0; g < 8; g++) {
    const int nl = g * 32 + lane;
    const bool valid = nl < CHN;
    const int n = n0 + nl;
    float kf[DHH];
#pragma unroll
    for (int t = 0; t < DHH; t++) kf[t] = valid ? gk[(size_t)t * NN + n] : 0.f;
#pragma unroll
    for (int t = 0; t < DHH; t++) v_s[h][t][lane] = valid ? gv[(size_t)t * NN + n] : 0.f;
#pragma unroll
    for (int mi = 0; mi < BEAM; mi++) {
      const float4* qv = (const float4*)&q_s[mi][h * DHH];
      float s = 0.f;
#pragma unroll
      for (int t4 = 0; t4 < 4; t4++) {
        float4 q4 = qv[t4];
        s = fmaf(q4.x, kf[t4 * 4 + 0], s);
        s = fmaf(q4.y, kf[t4 * 4 + 1], s);
        s = fmaf(q4.z, kf[t4 * 4 + 2], s);
        s = fmaf(q4.w, kf[t4 * 4 + 3], s);
      }
      s_s[h][mi][lane] = valid ? s * 0.25f : -1e30f;
    }
    __syncwarp();
    float gm = -1e30f;
#pragma unroll
    for (int j = 0; j < 32; j++) {
      float s = mk[mown][g * 32 + j] ? -1e30f : s_s[h][mown][j];
      s_s[h][mown][j] = s;
      gm = fmaxf(gm, s);
    }
    float mnew = fmaxf(m_run, gm);
    float scale = fexp(m_run - mnew);
    float ssum = 0.f;
#pragma unroll
    for (int j = 0; j < 8; j++) acc[j] *= scale;
#pragma unroll
    for (int j = 0; j < 32; j++) {
      float p = fexp(s_s[h][mown][j] - mnew);
      ssum += p;
#pragma unroll
      for (int jj = 0; jj < 8; jj++) acc[jj] = fmaf(p, v_s[h][tg * 8 + jj][j], acc[jj]);
    }
    s_run = s_run * scale + ssum;
    m_run = mnew;
    __syncwarp();
  }
  const int idx = ((b * NCHUNK + c) * HH + h) * BEAM + mown;
  if (tg == 0) { g_pm[idx] = m_run; g_ps[idx] = s_run; }
#pragma unroll
  for (int j = 0; j < 8; j++) g_pacc[idx * DHH + tg * 8 + j] = acc[j];
}

// ---------------------------------------------------------------------------
// K5: reduce partials -> heads -> glim2 = heads @ M_T
// ---------------------------------------------------------------------------
__global__ __launch_bounds__(128) void reduce_kernel() {
  const int bm = blockIdx.x;
  const int b = bm >> 4;
  const int m = bm & 15;
  const int d = threadIdx.x;
  const int h = d >> 4;
  const int t = d & 15;
  __shared__ float heads[DD];
  float M = -1e30f, S = 0.f, A = 0.f;
#pragma unroll
  for (int c = 0; c < NCHUNK; c++) {
    const int idx = ((b * NCHUNK + c) * HH + h) * BEAM + m;
    float mc = g_pm[idx];
    float sc = g_ps[idx];
    float ac = g_pacc[idx * DHH + t];
    float mn = fmaxf(M, mc);
    float e1 = fexp(M - mn);
    float e2 = fexp(mc - mn);
    S = S * e1 + sc * e2;
    A = A * e1 + ac * e2;
    M = mn;
  }
  heads[d] = A / S;
  __syncthreads();
  float a = 0.f;
#pragma unroll 8
  for (int k = 0; k < DD; k++) a = fmaf(heads[k], g_Mt[k * DD + d], a);
  g_glim[bm * DD + d] = a;
}

// ---------------------------------------------------------------------------
// K6: beam-batched logits vs transposed emb (raw mask read)
// ---------------------------------------------------------------------------
__global__ __launch_bounds__(256) void logits_kernel(const unsigned char* __restrict__ mask,
                                                     float* __restrict__ out) {
  const int b = blockIdx.x, c = blockIdx.y;
  const int tid = threadIdx.x;
  __shared__ float glim_s[BEAM][DD];
  __shared__ unsigned char mk[BEAM][260];
  for (int i = tid; i < BEAM * DD; i += 256) glim_s[i >> 7][i & 127] = g_glim[b * BEAM * DD + i];
  for (int i = tid; i < BEAM * 256; i += 256) {
    int m = i >> 8, n = i & 255;
    mk[m][n] = (n < CHN) ? mask_at(mask, (size_t)(b * BEAM + m) * NN + c * CHN + n) : (unsigned char)1;
  }
  __syncthreads();
  if (tid >= CHN) return;
  const int n = c * CHN + tid;
  const float* __restrict__ lk = g_et + (size_t)b * DD * NN + n;
  float s[BEAM];
#pragma unroll
  for (int m = 0; m < BEAM; m++) s[m] = 0.f;
#pragma unroll 4
  for (int f = 0; f < DD; f += 4) {
    float l0 = lk[(size_t)(f + 0) * NN];
    float l1 = lk[(size_t)(f + 1) * NN];
    float l2 = lk[(size_t)(f + 2) * NN];
    float l3 = lk[(size_t)(f + 3) * NN];
#pragma unroll
    for (int m = 0; m < BEAM; m++) {
      float4 g4 = *(const float4*)&glim_s[m][f];
      s[m] = fmaf(g4.x, l0, s[m]);
      s[m] = fmaf(g4.y, l1, s[m]);
      s[m] = fmaf(g4.z, l2, s[m]);
      s[m] = fmaf(g4.w, l3, s[m]);
    }
  }
  const float invsq = 0.08838834764831845f;
#pragma unroll
  for (int m = 0; m < BEAM; m++) {
    float v = 10.f * tanhf(s[m] * invsq);
    if (mk[m][tid]) v = -FLT_MAX;
    out[((size_t)(b * BEAM + m)) * NN + n] = v;
  }
}

// ---------------------------------------------------------------------------
// K7: finalize per (b,m): log_softmax + top3
// ---------------------------------------------------------------------------
__global__ __launch_bounds__(256) void finalize_kernel(float* __restrict__ out) {
  const int bm = blockIdx.x;
  const int tid = threadIdx.x;
  float* __restrict__ lp = out + (size_t)bm * NN;
  __shared__ float logits[NN];
  __shared__ float red[256];
  __shared__ float stv[256][3];
  __shared__ int sti[256][3];

  float tv0 = -INFINITY, tv1 = -INFINITY, tv2 = -INFINITY;
  int ti0 = 0, ti1 = 0, ti2 = 0;
  float lmax = -INFINITY;
#pragma unroll 1
  for (int k = 0; k < 8; k++) {
    const int n = tid + 256 * k;
    if (n >= NN) break;
    float v = lp[n];
    logits[n] = v;
    lmax = fmaxf(lmax, v);
    if (v > tv0) { tv2 = tv1; ti2 = ti1; tv1 = tv0; ti1 = ti0; tv0 = v; ti0 = n; }
    else if (v > tv1) { tv2 = tv1; ti2 = ti1; tv1 = v; ti1 = n; }
    else if (v > tv2) { tv2 = v; ti2 = n; }
  }
  stv[tid][0] = tv0; stv[tid][1] = tv1; stv[tid][2] = tv2;
  sti[tid][0] = ti0; sti[tid][1] = ti1; sti[tid][2] = ti2;
  red[tid] = lmax;
  __syncthreads();
  for (int s2 = 128; s2 > 0; s2 >>= 1) {
    if (tid < s2) red[tid] = fmaxf(red[tid], red[tid + s2]);
    __syncthreads();
  }
  lmax = red[0];
  __syncthreads();
  float lsum = 0.f;
  for (int n = tid; n < NN; n += 256) lsum += fexp(logits[n] - lmax);
  red[tid] = lsum;
  __syncthreads();
  for (int s2 = 128; s2 > 0; s2 >>= 1) {
    if (tid < s2) red[tid] += red[tid + s2];
    __syncthreads();
  }
  const float lse = lmax + __logf(red[0]);

  for (int n = tid; n < NN; n += 256) lp[n] = logits[n] - lse;

  for (int s2 = 128; s2 > 0; s2 >>= 1) {
    if (tid < s2) {
      float a0 = stv[tid][0], a1 = stv[tid][1], a2 = stv[tid][2];
      int i0 = sti[tid][0], i1 = sti[tid][1], i2 = sti[tid][2];
#pragma unroll
      for (int j = 0; j < 3; j++) {
        float v = stv[tid + s2][j];
        int ii = sti[tid + s2][j];
        if (v > a0) { a2 = a1; i2 = i1; a1 = a0; i1 = i0; a0 = v; i0 = ii; }
        else if (v > a1) { a2 = a1; i2 = i1; a1 = v; i1 = ii; }
        else if (v > a2) { a2 = v; i2 = ii; }
      }
      stv[tid][0] = a0; stv[tid][1] = a1; stv[tid][2] = a2;
      sti[tid][0] = i0; sti[tid][1] = i1; sti[tid][2] = i2;
    }
    __syncthreads();
  }
  if (tid == 0) {
    float* tvo = out + (size_t)BB * BEAM * NN + bm * 3;
    float* tio = out + (size_t)BB * BEAM * NN + (size_t)BB * BEAM * 3 + bm * 3;
    tvo[0] = stv[0][0] - lse; tvo[1] = stv[0][1] - lse; tvo[2] = stv[0][2] - lse;
    tio[0] = (float)sti[0][0]; tio[1] = (float)sti[0][1]; tio[2] = (float)sti[0][2];
  }
}

// ---------------------------------------------------------------------------
extern "C" void kernel_launch(void* const* d_in, const int* in_sizes, int n_in,
                              void* d_out, int out_size) {
  const float* emb = nullptr;
  const float* W_node = nullptr;
  const float* W_fixed = nullptr;
  const float* W_step = nullptr;
  const float* W_out = nullptr;
  const int* seq = nullptr;
  const unsigned char* mask = nullptr;
  for (int i = 0; i < n_in; i++) {
    int sz = in_sizes[i];
    if (sz == BB * NN * DD) emb = (const float*)d_in[i];
    else if (sz == DD * 3 * DD) W_node = (const float*)d_in[i];
    else if (sz == 2 * DD * DD) W_step = (const float*)d_in[i];
    else if (sz == BB * BEAM * 2) seq = (const int*)d_in[i];
    else if (sz == BB * BEAM * NN) mask = (const unsigned char*)d_in[i];
    else if (sz == DD * DD) {
      if (!W_fixed) W_fixed = (const float*)d_in[i];
      else W_out = (const float*)d_in[i];
    }
  }
  float* out = (float*)d_out;

  static int smem_set = 0;
  if (!smem_set) {
    cudaFuncSetAttribute(kvl_gemm, cudaFuncAttributeMaxDynamicSharedMemorySize,
                         4 * TS * (int)sizeof(float));
    smem_set = 1;
  }

  detect_mask_kernel<<<64, 256>>>(mask);
  fpart_kernel<<<dim3(BB, NCHUNK), 512>>>(emb);
  kvl_gemm<<<dim3(2, (BB * NN) / 128), 256, 4 * TS * sizeof(float)>>>(emb, W_node);
  etrans_kernel<<<dim3(63, 4, BB), dim3(32, 8)>>>(emb);
  mt_kernel<<<64, 256>>>(W_node, W_out);
  query_kernel<<<BB * BEAM, 128>>>(emb, W_fixed, W_step, seq);
  glimpse_kernel<<<dim3(BB, NCHUNK), 256>>>(mask);
  reduce_kernel<<<BB * BEAM, 128>>>();
  logits_kernel<<<dim3(BB, NCHUNK), 256>>>(mask, out);
  finalize_kernel<<<BB * BEAM, 256>>>(out);
}

// round 17
// speedup vs baseline: 1.7874x; 1.0447x over previous
#include <cuda_runtime.h>
#include <cstdint>
#include <cfloat>
#include <math.h>

// Problem constants
#define BB 64
#define NN 2000
#define DD 128
#define HH 8
#define DHH 16
#define BEAM 16
#define NCHUNK 8
#define CHN 250

// Scratch
__device__ float g_kt[(size_t)BB * 256 * NN + 64];        // feature-major gk|gv
__device__ float g_et[(size_t)BB * 128 * NN + 64];        // feature-major emb
__device__ float g_Mt[DD * DD];                           // M_T[k][d]
__device__ int g_isbool;
__device__ float g_fpart[BB * NCHUNK * DD];
__device__ float g_q[BB * BEAM * DD];
__device__ float g_pm[BB * NCHUNK * HH * BEAM];
__device__ float g_ps[BB * NCHUNK * HH * BEAM];
__device__ float g_pacc[BB * NCHUNK * HH * BEAM * DHH];
__device__ float g_glim[BB * BEAM * DD];

// fma-pipe exp for x <= 0
__device__ __forceinline__ float fexp(float x) {
  x = fmaxf(x, -80.f);
  float y = x * 1.4426950408889634f;
  float r = y + 12582912.f;
  float k = r - 12582912.f;
  float f = y - k;
  float p = 1.5403530393381609e-4f;
  p = fmaf(p, f, 1.3333558146428443e-3f);
  p = fmaf(p, f, 9.6181291976353993e-3f);
  p = fmaf(p, f, 5.5504108664821580e-2f);
  p = fmaf(p, f, 2.4022650695910071e-1f);
  p = fmaf(p, f, 6.9314718055994531e-1f);
  p = fmaf(p, f, 1.0f);
  int e = (int)k;
  return p * __int_as_float((e + 127) << 23);
}

__device__ __forceinline__ void cp16(void* sptr, const void* gptr) {
  unsigned int saddr = (unsigned int)__cvta_generic_to_shared(sptr);
  asm volatile("cp.async.cg.shared.global [%0], [%1], 16;" :: "r"(saddr), "l"(gptr));
}

// packed fp32x2 FMA: c = a*b + c elementwise on 2 floats
__device__ __forceinline__ void ffma2(unsigned long long& c, unsigned long long a,
                                      unsigned long long b) {
  asm("fma.rn.f32x2 %0, %1, %2, %0;" : "+l"(c) : "l"(a), "l"(b));
}
__device__ __forceinline__ unsigned long long pack2(float lo, float hi) {
  unsigned long long r;
  asm("mov.b64 %0, {%1, %2};" : "=l"(r) : "f"(lo), "f"(hi));
  return r;
}
__device__ __forceinline__ void unpack2(unsigned long long v, float& lo, float& hi) {
  asm("mov.b64 {%0, %1}, %2;" : "=f"(lo), "=f"(hi) : "l"(v));
}

// mask element read (handles bool-byte or int32 encodings)
__device__ __forceinline__ unsigned char mask_at(const unsigned char* m, size_t idx) {
  if (g_isbool) return (unsigned char)(m[idx] != 0);
  return (unsigned char)(((const int*)m)[idx] != 0);
}

// ---------------- mask detect / fpart ----------------
__global__ __launch_bounds__(256) void detect_mask_kernel(const unsigned char* __restrict__ m) {
  int base = blockIdx.x * (1 << 14);
  int local = 0;
  for (int i = threadIdx.x; i < (1 << 14); i += 256) {
    int idx = base + i;
    if ((idx & 3) && m[idx]) local = 1;
  }
  if (__syncthreads_or(local)) {
    if (threadIdx.x == 0) g_isbool = 1;
  }
}

__global__ __launch_bounds__(512) void fpart_kernel(const float* __restrict__ emb) {
  int b = blockIdx.x, c = blockIdx.y;
  int r = threadIdx.x >> 7, d = threadIdx.x & 127;
  __shared__ float part[4][DD];
  const float* p = emb + ((size_t)b * NN + c * CHN) * DD + d;
  float s = 0.f;
#pragma unroll 4
  for (int n = r; n < CHN; n += 4) s += p[(size_t)n * DD];
  part[r][d] = s;
  __syncthreads();
  if (r == 0)
    g_fpart[(b * NCHUNK + c) * DD + d] = part[0][d] + part[1][d] + part[2][d] + part[3][d];
}

// ---------------------------------------------------------------------------
// Transpose emb -> g_et[b][d][n]. grid (63, 4, 64), block (32, 8).
// ---------------------------------------------------------------------------
__global__ __launch_bounds__(256) void etrans_kernel(const float* __restrict__ emb) {
  __shared__ float t[32][33];
  const int n0 = blockIdx.x * 32, d0 = blockIdx.y * 32, b = blockIdx.z;
  const int tx = threadIdx.x, ty = threadIdx.y;
#pragma unroll
  for (int r = 0; r < 4; r++) {
    int n = n0 + ty + 8 * r;
    if (n < NN) t[ty + 8 * r][tx] = emb[((size_t)b * NN + n) * DD + d0 + tx];
  }
  __syncthreads();
#pragma unroll
  for (int r = 0; r < 4; r++) {
    int n = n0 + tx;
    int d = d0 + ty + 8 * r;
    if (n < NN) g_et[((size_t)b * DD + d) * NN + n] = t[tx][ty + 8 * r];
  }
}

// ---------------------------------------------------------------------------
// M_T[k][d] = sum_t W_out[k][t] * W_node[d*384+256+t]
// ---------------------------------------------------------------------------
__global__ __launch_bounds__(256) void mt_kernel(const float* __restrict__ W_node,
                                                 const float* __restrict__ W_out) {
  int idx = blockIdx.x * 256 + threadIdx.x;
  int k = idx >> 7, d = idx & 127;
  const float* wo = W_out + k * DD;
  const float* wl = W_node + (size_t)d * 384 + 256;
  float s = 0.f;
#pragma unroll 8
  for (int t = 0; t < DD; t++) s = fmaf(wo[t], wl[t], s);
  g_Mt[k * DD + d] = s;
}

// ---------------------------------------------------------------------------
// K2: [gk|gv] = emb @ W_node[:,0:256] via packed f32x2 FMA.
// Warp geometry remapped to 8(m)x4(n) lanes per warp (warps tiled 2x4) to
// cut B-fragment LDS wavefronts 4->1 (A 1->2; net 10->6 per warp per k).
// grid (2, 1000), 256 threads, 2 CTAs/SM.
// ---------------------------------------------------------------------------
#define TS 4224  // 32*132 floats per stage
__global__ __launch_bounds__(256, 2) void kvl_gemm(
    const float* __restrict__ A, const float* __restrict__ W) {
  extern __shared__ float smem[];  // As[2][32][132] | Bs[2][32][132]
  float* Bs_base = smem + 2 * TS;
  const int m0 = blockIdx.y * 128;
  const int n0 = blockIdx.x * 128;
  const int tid = threadIdx.x;
  // warp-geometry remap: bijection on 16x16 thread grid
  const int tx = ((tid >> 6) << 2) | ((tid >> 3) & 3);   // n micro 0..15
  const int ty = (((tid >> 5) & 1) << 3) | (tid & 7);    // m micro 0..15
  const int lrA = tid >> 3;
  const int lcA = (tid & 7) * 4;
  const int wrB = tid >> 5;
  const int wcB = (tid & 31) * 4;

  unsigned long long acc2[8][4];
#pragma unroll
  for (int i = 0; i < 8; i++)
#pragma unroll
    for (int jp = 0; jp < 4; jp++) acc2[i][jp] = 0ull;

  auto cp_b = [&](int st, int kb) {
#pragma unroll
    for (int p = 0; p < 4; p++) {
      int kr = wrB + 8 * p;
      cp16(&Bs_base[st * TS + kr * 132 + wcB], &W[(size_t)(kb + kr) * 384 + n0 + wcB]);
    }
    asm volatile("cp.async.commit_group;");
  };
  auto ldg_a = [&](int kb, float4* r) {
#pragma unroll
    for (int p = 0; p < 4; p++)
      r[p] = *(const float4*)&A[(size_t)(m0 + lrA + 32 * p) * 128 + kb + lcA];
  };
  auto sts_a = [&](int st, const float4* r) {
#pragma unroll
    for (int p = 0; p < 4; p++) {
      int row = lrA + 32 * p;
      smem[st * TS + (lcA + 0) * 132 + row] = r[p].x;
      smem[st * TS + (lcA + 1) * 132 + row] = r[p].y;
      smem[st * TS + (lcA + 2) * 132 + row] = r[p].z;
      smem[st * TS + (lcA + 3) * 132 + row] = r[p].w;
    }
  };

  float4 areg[4];
  cp_b(0, 0);
  ldg_a(0, areg);
  sts_a(0, areg);

#pragma unroll 1
  for (int it = 0; it < 4; it++) {
    if (it < 3) {
      cp_b((it + 1) & 1, (it + 1) * 32);
      ldg_a((it + 1) * 32, areg);
      asm volatile("cp.async.wait_group 1;");
    } else {
      asm volatile("cp.async.wait_group 0;");
    }
    __syncthreads();
    const float* As = smem + (it & 1) * TS;
    const float* Bs = Bs_base + (it & 1) * TS;
#pragma unroll 8
    for (int k = 0; k < 32; k++) {
      float a[8], bf[8];
      *(float4*)&a[0] = *(const float4*)&As[k * 132 + ty * 8];
      *(float4*)&a[4] = *(const float4*)&As[k * 132 + ty * 8 + 4];
      *(float4*)&bf[0] = *(const float4*)&Bs[k * 132 + tx * 8];
      *(float4*)&bf[4] = *(const float4*)&Bs[k * 132 + tx * 8 + 4];
      unsigned long long b2[4];
#pragma unroll
      for (int jp = 0; jp < 4; jp++) b2[jp] = pack2(bf[2 * jp], bf[2 * jp + 1]);
#pragma unroll
      for (int i = 0; i < 8; i++) {
        unsigned long long a2 = pack2(a[i], a[i]);
#pragma unroll
        for (int jp = 0; jp < 4; jp++) ffma2(acc2[i][jp], a2, b2[jp]);
      }
    }
    if (it < 3) sts_a((it + 1) & 1, areg);
    __syncthreads();
  }

  // unpack accumulators
  float acc[8][8];
#pragma unroll
  for (int i = 0; i < 8; i++)
#pragma unroll
    for (int jp = 0; jp < 4; jp++) unpack2(acc2[i][jp], acc[i][2 * jp], acc[i][2 * jp + 1]);

  // --- transpose epilogue (depends only on (tx,ty) bijection; unchanged) ---
  float* Es = smem;
#pragma unroll 1
  for (int c = 0; c < 4; c++) {
    if ((tx >> 2) == c) {
#pragma unroll
      for (int i = 0; i < 8; i++)
#pragma unroll
        for (int j = 0; j < 8; j++)
          Es[((tx - 4 * c) * 8 + j) * 132 + ty * 8 + i] = acc[i][j];
    }
    __syncthreads();
#pragma unroll
    for (int j4 = 0; j4 < 4; j4++) {
      int fr = (tid >> 5) + 8 * j4;
      int mloc = (tid & 31) * 4;
      int gf = n0 + 32 * c + fr;
#pragma unroll
      for (int e = 0; e < 4; e++) {
        int m = m0 + mloc + e;
        int b = m / NN;
        int n = m - b * NN;
        g_kt[((size_t)b * 256 + gf) * NN + n] = Es[fr * 132 + mloc + e];
      }
    }
    __syncthreads();
  }
}

// ---------------------------------------------------------------------------
// K3: query build
// ---------------------------------------------------------------------------
__global__ __launch_bounds__(128) void query_kernel(
    const float* __restrict__ emb, const float* __restrict__ W_fixed,
    const float* __restrict__ W_step, const int* __restrict__ seq) {
  const int bm = blockIdx.x;
  const int b = bm >> 4;
  const int d = threadIdx.x;
  __shared__ float mean[DD], ef[DD], el[DD];
  float s = 0.f;
#pragma unroll
  for (int c = 0; c < NCHUNK; c++) s += g_fpart[(b * NCHUNK + c) * DD + d];
  mean[d] = s * (1.0f / (float)NN);
  int fidx = seq[bm * 2];
  int lidx = seq[bm * 2 + 1];
  ef[d] = emb[((size_t)b * NN + fidx) * DD + d];
  el[d] = emb[((size_t)b * NN + lidx) * DD + d];
  __syncthreads();
  float a = 0.f;
#pragma unroll 8
  for (int k = 0; k < DD; k++) a = fmaf(mean[k], W_fixed[k * DD + d], a);
#pragma unroll 8
  for (int k = 0; k < DD; k++) a = fmaf(ef[k], W_step[k * DD + d], a);
#pragma unroll 8
  for (int k = 0; k < DD; k++) a = fmaf(el[k], W_step[(DD + k) * DD + d], a);
  g_q[bm * DD + d] = a;
}

// ---------------------------------------------------------------------------
// K4: beam-batched glimpse partials (raw mask read)
// ---------------------------------------------------------------------------
__global__ __launch_bounds__(256) void glimpse_kernel(const unsigned char* __restrict__ mask) {
  const int b = blockIdx.x, c = blockIdx.y;
  const int n0 = c * CHN;
  const int tid = threadIdx.x;
  const int h = tid >> 5;
  const int lane = tid & 31;

  __shared__ float q_s[BEAM][DD];
  __shared__ unsigned char mk[BEAM][260];
  __shared__ float s_s[HH][BEAM][33];
  __shared__ float v_s[HH][DHH][33];

  for (int i = tid; i < BEAM * DD; i += 256) q_s[i >> 7][i & 127] = g_q[b * BEAM * DD + i];
  for (int i = tid; i < BEAM * 256; i += 256) {
    int m = i >> 8, n = i & 255;
    mk[m][n] = (n < CHN) ? mask_at(mask, (size_t)(b * BEAM + m) * NN + n0 + n) : (unsigned char)1;
  }
  __syncthreads();

  const float* __restrict__ gk = g_kt + ((size_t)b * 256 + h * DHH) * NN;
  const float* __restrict__ gv = g_kt + ((size_t)b * 256 + 128 + h * DHH) * NN;

  const int mown = lane & 15;
  const int tg = lane >> 4;
  float m_run = -1e30f, s_run = 0.f;
  float acc[8];
#pragma unroll
  for (int j = 0; j < 8; j++) acc[j] = 0.f;

#pragma unroll 1
  for (int g = 0; g < 8; g++) {
    const int nl = g * 32 + lane;
    const bool valid = nl < CHN;
    const int n = n0 + nl;
    float kf[DHH];
#pragma unroll
    for (int t = 0; t < DHH; t++) kf[t] = valid ? gk[(size_t)t * NN + n] : 0.f;
#pragma unroll
    for (int t = 0; t < DHH; t++) v_s[h][t][lane] = valid ? gv[(size_t)t * NN + n] : 0.f;
#pragma unroll
    for (int mi = 0; mi < BEAM; mi++) {
      const float4* qv = (const float4*)&q_s[mi][h * DHH];
      float s = 0.f;
#pragma unroll
      for (int t4 = 0; t4 < 4; t4++) {
        float4 q4 = qv[t4];
        s = fmaf(q4.x, kf[t4 * 4 + 0], s);
        s = fmaf(q4.y, kf[t4 * 4 + 1], s);
        s = fmaf(q4.z, kf[t4 * 4 + 2], s);
        s = fmaf(q4.w, kf[t4 * 4 + 3], s);
      }
      s_s[h][mi][lane] = valid ? s * 0.25f : -1e30f;
    }
    __syncwarp();
    float gm = -1e30f;
#pragma unroll
    for (int j = 0; j < 32; j++) {
      float s = mk[mown][g * 32 + j] ? -1e30f : s_s[h][mown][j];
      s_s[h][mown][j] = s;
      gm = fmaxf(gm, s);
    }
    float mnew = fmaxf(m_run, gm);
    float scale = fexp(m_run - mnew);
    float ssum = 0.f;
#pragma unroll
    for (int j = 0; j < 8; j++) acc[j] *= scale;
#pragma unroll
    for (int j = 0; j < 32; j++) {
      float p = fexp(s_s[h][mown][j] - mnew);
      ssum += p;
#pragma unroll
      for (int jj = 0; jj < 8; jj++) acc[jj] = fmaf(p, v_s[h][tg * 8 + jj][j], acc[jj]);
    }
    s_run = s_run * scale + ssum;
    m_run = mnew;
    __syncwarp();
  }
  const int idx = ((b * NCHUNK + c) * HH + h) * BEAM + mown;
  if (tg == 0) { g_pm[idx] = m_run; g_ps[idx] = s_run; }
#pragma unroll
  for (int j = 0; j < 8; j++) g_pacc[idx * DHH + tg * 8 + j] = acc[j];
}

// ---------------------------------------------------------------------------
// K5: reduce partials -> heads -> glim2 = heads @ M_T
// ---------------------------------------------------------------------------
__global__ __launch_bounds__(128) void reduce_kernel() {
  const int bm = blockIdx.x;
  const int b = bm >> 4;
  const int m = bm & 15;
  const int d = threadIdx.x;
  const int h = d >> 4;
  const int t = d & 15;
  __shared__ float heads[DD];
  float M = -1e30f, S = 0.f, A = 0.f;
#pragma unroll
  for (int c = 0; c < NCHUNK; c++) {
    const int idx = ((b * NCHUNK + c) * HH + h) * BEAM + m;
    float mc = g_pm[idx];
    float sc = g_ps[idx];
    float ac = g_pacc[idx * DHH + t];
    float mn = fmaxf(M, mc);
    float e1 = fexp(M - mn);
    float e2 = fexp(mc - mn);
    S = S * e1 + sc * e2;
    A = A * e1 + ac * e2;
    M = mn;
  }
  heads[d] = A / S;
  __syncthreads();
  float a = 0.f;
#pragma unroll 8
  for (int k = 0; k < DD; k++) a = fmaf(heads[k], g_Mt[k * DD + d], a);
  g_glim[bm * DD + d] = a;
}

// ---------------------------------------------------------------------------
// K6: beam-batched logits vs transposed emb (raw mask read)
// ---------------------------------------------------------------------------
__global__ __launch_bounds__(256) void logits_kernel(const unsigned char* __restrict__ mask,
                                                     float* __restrict__ out) {
  const int b = blockIdx.x, c = blockIdx.y;
  const int tid = threadIdx.x;
  __shared__ float glim_s[BEAM][DD];
  __shared__ unsigned char mk[BEAM][260];
  for (int i = tid; i < BEAM * DD; i += 256) glim_s[i >> 7][i & 127] = g_glim[b * BEAM * DD + i];
  for (int i = tid; i < BEAM * 256; i += 256) {
    int m = i >> 8, n = i & 255;
    mk[m][n] = (n < CHN) ? mask_at(mask, (size_t)(b * BEAM + m) * NN + c * CHN + n) : (unsigned char)1;
  }
  __syncthreads();
  if (tid >= CHN) return;
  const int n = c * CHN + tid;
  const float* __restrict__ lk = g_et + (size_t)b * DD * NN + n;
  float s[BEAM];
#pragma unroll
  for (int m = 0; m < BEAM; m++) s[m] = 0.f;
#pragma unroll 4
  for (int f = 0; f < DD; f += 4) {
    float l0 = lk[(size_t)(f + 0) * NN];
    float l1 = lk[(size_t)(f + 1) * NN];
    float l2 = lk[(size_t)(f + 2) * NN];
    float l3 = lk[(size_t)(f + 3) * NN];
#pragma unroll
    for (int m = 0; m < BEAM; m++) {
      float4 g4 = *(const float4*)&glim_s[m][f];
      s[m] = fmaf(g4.x, l0, s[m]);
      s[m] = fmaf(g4.y, l1, s[m]);
      s[m] = fmaf(g4.z, l2, s[m]);
      s[m] = fmaf(g4.w, l3, s[m]);
    }
  }
  const float invsq = 0.08838834764831845f;
#pragma unroll
  for (int m = 0; m < BEAM; m++) {
    float v = 10.f * tanhf(s[m] * invsq);
    if (mk[m][tid]) v = -FLT_MAX;
    out[((size_t)(b * BEAM + m)) * NN + n] = v;
  }
}

// ---------------------------------------------------------------------------
// K7: finalize per (b,m): log_softmax + top3
// ---------------------------------------------------------------------------
__global__ __launch_bounds__(256) void finalize_kernel(float* __restrict__ out) {
  const int bm = blockIdx.x;
  const int tid = threadIdx.x;
  float* __restrict__ lp = out + (size_t)bm * NN;
  __shared__ float logits[NN];
  __shared__ float red[256];
  __shared__ float stv[256][3];
  __shared__ int sti[256][3];

  float tv0 = -INFINITY, tv1 = -INFINITY, tv2 = -INFINITY;
  int ti0 = 0, ti1 = 0, ti2 = 0;
  float lmax = -INFINITY;
#pragma unroll 1
  for (int k = 0; k < 8; k++) {
    const int n = tid + 256 * k;
    if (n >= NN) break;
    float v = lp[n];
    logits[n] = v;
    lmax = fmaxf(lmax, v);
    if (v > tv0) { tv2 = tv1; ti2 = ti1; tv1 = tv0; ti1 = ti0; tv0 = v; ti0 = n; }
    else if (v > tv1) { tv2 = tv1; ti2 = ti1; tv1 = v; ti1 = n; }
    else if (v > tv2) { tv2 = v; ti2 = n; }
  }
  stv[tid][0] = tv0; stv[tid][1] = tv1; stv[tid][2] = tv2;
  sti[tid][0] = ti0; sti[tid][1] = ti1; sti[tid][2] = ti2;
  red[tid] = lmax;
  __syncthreads();
  for (int s2 = 128; s2 > 0; s2 >>= 1) {
    if (tid < s2) red[tid] = fmaxf(red[tid], red[tid + s2]);
    __syncthreads();
  }
  lmax = red[0];
  __syncthreads();
  float lsum = 0.f;
  for (int n = tid; n < NN; n += 256) lsum += fexp(logits[n] - lmax);
  red[tid] = lsum;
  __syncthreads();
  for (int s2 = 128; s2 > 0; s2 >>= 1) {
    if (tid < s2) red[tid] += red[tid + s2];
    __syncthreads();
  }
  const float lse = lmax + __logf(red[0]);

  for (int n = tid; n < NN; n += 256) lp[n] = logits[n] - lse;

  for (int s2 = 128; s2 > 0; s2 >>= 1) {
    if (tid < s2) {
      float a0 = stv[tid][0], a1 = stv[tid][1], a2 = stv[tid][2];
      int i0 = sti[tid][0], i1 = sti[tid][1], i2 = sti[tid][2];
#pragma unroll
      for (int j = 0; j < 3; j++) {
        float v = stv[tid + s2][j];
        int ii = sti[tid + s2][j];
        if (v > a0) { a2 = a1; i2 = i1; a1 = a0; i1 = i0; a0 = v; i0 = ii; }
        else if (v > a1) { a2 = a1; i2 = i1; a1 = v; i1 = ii; }
        else if (v > a2) { a2 = v; i2 = ii; }
      }
      stv[tid][0] = a0; stv[tid][1] = a1; stv[tid][2] = a2;
      sti[tid][0] = i0; sti[tid][1] = i1; sti[tid][2] = i2;
    }
    __syncthreads();
  }
  if (tid == 0) {
    float* tvo = out + (size_t)BB * BEAM * NN + bm * 3;
    float* tio = out + (size_t)BB * BEAM * NN + (size_t)BB * BEAM * 3 + bm * 3;
    tvo[0] = stv[0][0] - lse; tvo[1] = stv[0][1] - lse; tvo[2] = stv[0][2] - lse;
    tio[0] = (float)sti[0][0]; tio[1] = (float)sti[0][1]; tio[2] = (float)sti[0][2];
  }
}

// ---------------------------------------------------------------------------
extern "C" void kernel_launch(void* const* d_in, const int* in_sizes, int n_in,
                              void* d_out, int out_size) {
  const float* emb = nullptr;
  const float* W_node = nullptr;
  const float* W_fixed = nullptr;
  const float* W_step = nullptr;
  const float* W_out = nullptr;
  const int* seq = nullptr;
  const unsigned char* mask = nullptr;
  for (int i = 0; i < n_in; i++) {
    int sz = in_sizes[i];
    if (sz == BB * NN * DD) emb = (const float*)d_in[i];
    else if (sz == DD * 3 * DD) W_node = (const float*)d_in[i];
    else if (sz == 2 * DD * DD) W_step = (const float*)d_in[i];
    else if (sz == BB * BEAM * 2) seq = (const int*)d_in[i];
    else if (sz == BB * BEAM * NN) mask = (const unsigned char*)d_in[i];
    else if (sz == DD * DD) {
      if (!W_fixed) W_fixed = (const float*)d_in[i];
      else W_out = (const float*)d_in[i];
    }
  }
  float* out = (float*)d_out;

  static int smem_set = 0;
  if (!smem_set) {
    cudaFuncSetAttribute(kvl_gemm, cudaFuncAttributeMaxDynamicSharedMemorySize,
                         4 * TS * (int)sizeof(float));
    smem_set = 1;
  }

  detect_mask_kernel<<<64, 256>>>(mask);
  fpart_kernel<<<dim3(BB, NCHUNK), 512>>>(emb);
  kvl_gemm<<<dim3(2, (BB * NN) / 128), 256, 4 * TS * sizeof(float)>>>(emb, W_node);
  etrans_kernel<<<dim3(63, 4, BB), dim3(32, 8)>>>(emb);
  mt_kernel<<<64, 256>>>(W_node, W_out);
  query_kernel<<<BB * BEAM, 128>>>(emb, W_fixed, W_step, seq);
  glimpse_kernel<<<dim3(BB, NCHUNK), 256>>>(mask);
  reduce_kernel<<<BB * BEAM, 128>>>();
  logits_kernel<<<dim3(BB, NCHUNK), 256>>>(mask, out);
  finalize_kernel<<<BB * BEAM, 256>>>(out);
}